// round 9
// baseline (speedup 1.0000x reference)
#include <cuda_runtime.h>
#include <cuda_bf16.h>
#include <cstdint>

// Problem constants
#define NROWS 16384      // B*L
#define CDIM  1024
#define MDIM  128
#define NSEG  256
#define SEGS  64
#define TCTX  132
#define PDIM  4
#define HEADS 8
#define HD    128

// ===================== helpers (base sm_103 PTX only) ======================
__device__ __forceinline__ uint32_t smem_u32(const void* p) {
    uint32_t a;
    asm("{ .reg .u64 t; cvta.to.shared.u64 t, %1; cvt.u32.u64 %0, t; }" : "=r"(a) : "l"(p));
    return a;
}
__device__ __forceinline__ void ldsm4(uint32_t* r, uint32_t a) {
    asm volatile("ldmatrix.sync.aligned.m8n8.x4.shared.b16 {%0,%1,%2,%3}, [%4];"
        : "=r"(r[0]), "=r"(r[1]), "=r"(r[2]), "=r"(r[3]) : "r"(a));
}
__device__ __forceinline__ void mma16816(float* c, const uint32_t* a, const uint32_t* b) {
    asm volatile(
        "mma.sync.aligned.m16n8k16.row.col.f32.bf16.bf16.f32 "
        "{%0,%1,%2,%3}, {%4,%5,%6,%7}, {%8,%9}, {%0,%1,%2,%3};"
        : "+f"(c[0]), "+f"(c[1]), "+f"(c[2]), "+f"(c[3])
        : "r"(a[0]), "r"(a[1]), "r"(a[2]), "r"(a[3]), "r"(b[0]), "r"(b[1]));
}
__device__ __forceinline__ void cpasync16(uint32_t dst, const void* src) {
    asm volatile("cp.async.cg.shared.global [%0], [%1], 16;" :: "r"(dst), "l"(src));
}
#define CP_COMMIT() asm volatile("cp.async.commit_group;" ::: "memory")
#define CP_WAIT2()  asm volatile("cp.async.wait_group 2;" ::: "memory")
#define CP_WAIT1()  asm volatile("cp.async.wait_group 1;" ::: "memory")
#define CP_WAIT0()  asm volatile("cp.async.wait_group 0;" ::: "memory")

// ---------------- scratch (device globals) ---------------------------------
__device__ float g_K2[CDIM*CDIM];
__device__ float g_V2[CDIM*CDIM];
__device__ float g_kpm[PDIM*CDIM];
__device__ float g_vpm[PDIM*CDIM];
__device__ float g_bkret[CDIM];
__device__ float g_bvret[CDIM];
__device__ float g_mA[NROWS*MDIM];
__device__ float g_qb[NROWS*CDIM];
__device__ float g_kctx[NSEG*TCTX*CDIM];
__device__ float g_vctx[NSEG*TCTX*CDIM];
__device__ float g_attno[NROWS*CDIM];
__device__ float g_gate[NROWS*CDIM];
// bf16 hi/lo
__device__ __nv_bfloat16 g_xh[NROWS*CDIM],  g_xl[NROWS*CDIM];
__device__ __nv_bfloat16 g_sh[NROWS*CDIM],  g_sl[NROWS*CDIM];
__device__ __nv_bfloat16 g_mbh[NROWS*MDIM], g_mbl[NROWS*MDIM];
__device__ __nv_bfloat16 g_q2h[CDIM*CDIM],  g_q2l[CDIM*CDIM];
__device__ __nv_bfloat16 g_k2h[CDIM*CDIM],  g_k2l[CDIM*CDIM];
__device__ __nv_bfloat16 g_v2h[CDIM*CDIM],  g_v2l[CDIM*CDIM];
__device__ __nv_bfloat16 g_amh[MDIM*CDIM],  g_aml[MDIM*CDIM];
__device__ __nv_bfloat16 g_kmh[CDIM*MDIM],  g_kml[CDIM*MDIM];
__device__ __nv_bfloat16 g_vmh[CDIM*MDIM],  g_vml[CDIM*MDIM];
__device__ __nv_bfloat16 g_woh[CDIM*CDIM],  g_wol[CDIM*CDIM];
__device__ __nv_bfloat16 g_gwh[CDIM*CDIM],  g_gwl[CDIM*CDIM];
__device__ __nv_bfloat16 g_owh[CDIM*CDIM],  g_owl[CDIM*CDIM];
__device__ __nv_bfloat16 g_mwqh[CDIM*CDIM], g_mwql[CDIM*CDIM];
__device__ __nv_bfloat16 g_mwkh[CDIM*CDIM], g_mwkl[CDIM*CDIM];
__device__ __nv_bfloat16 g_mwvh[CDIM*CDIM], g_mwvl[CDIM*CDIM];
__device__ __nv_bfloat16 g_wqth[CDIM*CDIM], g_wqtl[CDIM*CDIM];
__device__ __nv_bfloat16 g_wkth[CDIM*CDIM], g_wktl[CDIM*CDIM];
__device__ __nv_bfloat16 g_wvth[CDIM*CDIM], g_wvtl[CDIM*CDIM];
__device__ __nv_bfloat16 g_mw1h[MDIM*CDIM], g_mw1l[MDIM*CDIM];
__device__ __nv_bfloat16 g_mowth[MDIM*CDIM], g_mowtl[MDIM*CDIM];
__device__ __nv_bfloat16 g_w2h[MDIM*MDIM],  g_w2l[MDIM*MDIM];

__device__ __forceinline__ uint32_t sw64(uint32_t b) { return b ^ ((b >> 3) & 0x30); }

#define MAXJ 8
struct TgBatch {
    int njobs;
    int prefix[MAXJ + 1];
    int tilesN[MAXJ];
    const __nv_bfloat16 *Ah[MAXJ], *Al[MAXJ], *Bh[MAXJ], *Bl[MAXJ];
    const float* bias[MAXJ];
    float* C[MAXJ];
    __nv_bfloat16 *Ch[MAXJ], *Cl[MAXJ];
    int K[MAXJ], N[MAXJ], sr[MAXJ], ss[MAXJ], ro[MAXJ];
};

// ============ 128x128-tile HMMA bf16x3 (256 thr) — N=128 jobs ==============
#define BK 32
#define TILE_B (128*BK*2)          // 8192
#define STG_B  (4*TILE_B)          // 32768
#define NSTG   3
#define TM_SMEM (NSTG*STG_B)       // 98304
__global__ __launch_bounds__(256, 2) void tmma_k(TgBatch bat)
{
    extern __shared__ char sm[];
    uint32_t sb = smem_u32(sm);
    int tid = threadIdx.x, wid = tid >> 5, lane = tid & 31;

    int bt = blockIdx.x;
    int j = 0;
#pragma unroll
    for (int t = 1; t < MAXJ; t++)
        if (t < bat.njobs && bt >= bat.prefix[t]) j = t;
    int local = bt - bat.prefix[j];
    int tN = bat.tilesN[j];
    int tileN = local % tN;
    int tileM = local / tN;

    const __nv_bfloat16* jAh = bat.Ah[j];
    const __nv_bfloat16* jAl = bat.Al[j];
    const __nv_bfloat16* jBh = bat.Bh[j];
    const __nv_bfloat16* jBl = bat.Bl[j];
    const float* jbias = bat.bias[j];
    float* jC = bat.C[j];
    __nv_bfloat16* jCh = bat.Ch[j];
    __nv_bfloat16* jCl = bat.Cl[j];
    int K = bat.K[j], N = bat.N[j];
    int seg_rows = bat.sr[j], seg_stride = bat.ss[j], row_off = bat.ro[j];

    int wm = wid & 1, wn = wid >> 1;

    int row_ld = tid >> 2, c16 = tid & 3;
    int row_ld1 = (tid + 256) >> 2, c161 = (tid + 256) & 3;
    uint32_t dst_sw0 = sw64((uint32_t)(row_ld * 64 + c16 * 16));
    uint32_t dst_sw1 = sw64((uint32_t)(row_ld1 * 64 + c161 * 16));

    const __nv_bfloat16* p0[4];
    ptrdiff_t pdel = (ptrdiff_t)(row_ld1 - row_ld) * K + (ptrdiff_t)(c161 - c16) * 8;
    {
        const __nv_bfloat16* base[4] = {
            jAh + (size_t)tileM * 128 * K, jAl + (size_t)tileM * 128 * K,
            jBh + (size_t)tileN * 128 * K, jBl + (size_t)tileN * 128 * K };
#pragma unroll
        for (int t = 0; t < 4; t++)
            p0[t] = base[t] + (size_t)row_ld * K + c16 * 8;
    }
    auto LOADS = [&](int stage) {
        uint32_t sbase = sb + stage * STG_B;
#pragma unroll
        for (int t = 0; t < 4; t++) {
            cpasync16(sbase + t * TILE_B + dst_sw0, p0[t]);
            cpasync16(sbase + t * TILE_B + dst_sw1, p0[t] + pdel);
            p0[t] += BK;
        }
    };

    int mi = lane >> 3, li = lane & 7;
    uint32_t arow[4], brow[2];
#pragma unroll
    for (int mt = 0; mt < 4; mt++)
        arow[mt] = (uint32_t)((wm * 64 + mt * 16 + (mi & 1) * 8 + li) * 64);
#pragma unroll
    for (int p = 0; p < 2; p++)
        brow[p] = (uint32_t)((wn * 32 + p * 16 + (mi & 1) * 8 + li) * 64);
    uint32_t kfr = (uint32_t)((mi >> 1) * 16);

    float acc[4][4][4];
#pragma unroll
    for (int a = 0; a < 4; a++)
#pragma unroll
        for (int b = 0; b < 4; b++)
#pragma unroll
            for (int r = 0; r < 4; r++) acc[a][b][r] = 0.f;

    int nchunk = K / BK;
    LOADS(0); CP_COMMIT();
    LOADS(1); CP_COMMIT();

    int cs = 0, ls = 2;
    for (int c = 0; c < nchunk; c++) {
        if (c + 2 < nchunk) {
            LOADS(ls); CP_COMMIT();
            if (++ls == NSTG) ls = 0;
            CP_WAIT2();
        } else if (c + 1 < nchunk) CP_WAIT1();
        else CP_WAIT0();
        __syncthreads();

        uint32_t sbase = sb + cs * STG_B;
        uint32_t bfh[4][2], bfl[4][2], afh[4], afl[4];
#pragma unroll
        for (int ks = 0; ks < 2; ks++) {
            uint32_t kb = kfr + ks * 32;
#pragma unroll
            for (int p = 0; p < 2; p++) {
                uint32_t r[4];
                ldsm4(r, sbase + 2 * TILE_B + sw64(brow[p] + kb));
                bfh[2 * p][0] = r[0]; bfh[2 * p][1] = r[2];
                bfh[2 * p + 1][0] = r[1]; bfh[2 * p + 1][1] = r[3];
                ldsm4(r, sbase + 3 * TILE_B + sw64(brow[p] + kb));
                bfl[2 * p][0] = r[0]; bfl[2 * p][1] = r[2];
                bfl[2 * p + 1][0] = r[1]; bfl[2 * p + 1][1] = r[3];
            }
#pragma unroll
            for (int mt = 0; mt < 4; mt++) {
                ldsm4(afh, sbase + 0 * TILE_B + sw64(arow[mt] + kb));
                ldsm4(afl, sbase + 1 * TILE_B + sw64(arow[mt] + kb));
#pragma unroll
                for (int nt = 0; nt < 4; nt++) mma16816(acc[mt][nt], afh, bfh[nt]);
#pragma unroll
                for (int nt = 0; nt < 4; nt++) mma16816(acc[mt][nt], afh, bfl[nt]);
#pragma unroll
                for (int nt = 0; nt < 4; nt++) mma16816(acc[mt][nt], afl, bfh[nt]);
            }
        }
        if (++cs == NSTG) cs = 0;
        __syncthreads();
    }

    int g = lane >> 2, t4 = lane & 3;
#pragma unroll
    for (int mt = 0; mt < 4; mt++) {
#pragma unroll
        for (int half = 0; half < 2; half++) {
            int rowg = tileM * 128 + wm * 64 + mt * 16 + half * 8 + g;
            int orow = (rowg / seg_rows) * seg_stride + row_off + (rowg % seg_rows);
            size_t rbase = (size_t)orow * N + tileN * 128 + wn * 32;
            const float* brows = jbias ? (jbias + tileN * 128 + wn * 32) : nullptr;
#pragma unroll
            for (int nt = 0; nt < 4; nt++) {
                int col = nt * 8 + t4 * 2;
                float vx = acc[mt][nt][half * 2 + 0];
                float vy = acc[mt][nt][half * 2 + 1];
                if (brows) { vx += brows[col]; vy += brows[col + 1]; }
                if (jC) *(float2*)(jC + rbase + col) = make_float2(vx, vy);
                if (jCh) {
                    __nv_bfloat16 hx = __float2bfloat16(vx);
                    __nv_bfloat16 hy = __float2bfloat16(vy);
                    *(__nv_bfloat162*)(jCh + rbase + col) = __nv_bfloat162(hx, hy);
                    *(__nv_bfloat162*)(jCl + rbase + col) = __nv_bfloat162(
                        __float2bfloat16(vx - __bfloat162float(hx)),
                        __float2bfloat16(vy - __bfloat162float(hy)));
                }
            }
        }
    }
}

// ============ 128x256-tile HMMA bf16x3 (512 thr) — N%256==0 jobs ===========
// smem/stage: Ah 8K | Al 8K | Bh 16K | Bl 16K = 48K; 3 stages = 144K.
#define T2_A  8192
#define T2_B  16384
#define S2_B  (2*T2_A + 2*T2_B)    // 49152
#define TM2_SMEM (NSTG*S2_B)       // 147456
__global__ __launch_bounds__(512, 1) void tmma256_k(TgBatch bat)
{
    extern __shared__ char sm[];
    uint32_t sb = smem_u32(sm);
    int tid = threadIdx.x, wid = tid >> 5, lane = tid & 31;

    int bt = blockIdx.x;
    int j = 0;
#pragma unroll
    for (int t = 1; t < MAXJ; t++)
        if (t < bat.njobs && bt >= bat.prefix[t]) j = t;
    int local = bt - bat.prefix[j];
    int tN = bat.tilesN[j];              // N/256
    int tileN = local % tN;
    int tileM = local / tN;

    const __nv_bfloat16* jAh = bat.Ah[j];
    const __nv_bfloat16* jAl = bat.Al[j];
    const __nv_bfloat16* jBh = bat.Bh[j];
    const __nv_bfloat16* jBl = bat.Bl[j];
    const float* jbias = bat.bias[j];
    float* jC = bat.C[j];
    __nv_bfloat16* jCh = bat.Ch[j];
    __nv_bfloat16* jCl = bat.Cl[j];
    int K = bat.K[j], N = bat.N[j];
    int seg_rows = bat.sr[j], seg_stride = bat.ss[j], row_off = bat.ro[j];

    int wm = wid & 1, wn = wid >> 1;     // 2 x 8 warp grid

    int row_ld = tid >> 2, c16 = tid & 3;        // 128 rows covered by 512 thr
    uint32_t dst_sw = sw64((uint32_t)(row_ld * 64 + c16 * 16));
    uint32_t dst_sw2 = sw64((uint32_t)((row_ld + 128) * 64 + c16 * 16));

    const __nv_bfloat16* pA0 = jAh + ((size_t)tileM * 128 + row_ld) * K + c16 * 8;
    const __nv_bfloat16* pA1 = jAl + ((size_t)tileM * 128 + row_ld) * K + c16 * 8;
    const __nv_bfloat16* pB0 = jBh + ((size_t)tileN * 256 + row_ld) * K + c16 * 8;
    const __nv_bfloat16* pB1 = jBl + ((size_t)tileN * 256 + row_ld) * K + c16 * 8;
    ptrdiff_t bdel = (ptrdiff_t)128 * K;

    auto LOADS = [&](int stage) {
        uint32_t sbase = sb + stage * S2_B;
        cpasync16(sbase + 0 * T2_A + dst_sw, pA0);
        cpasync16(sbase + 1 * T2_A + dst_sw, pA1);
        cpasync16(sbase + 2 * T2_A + dst_sw, pB0);
        cpasync16(sbase + 2 * T2_A + dst_sw2, pB0 + bdel);
        cpasync16(sbase + 2 * T2_A + T2_B + dst_sw, pB1);
        cpasync16(sbase + 2 * T2_A + T2_B + dst_sw2, pB1 + bdel);
        pA0 += BK; pA1 += BK; pB0 += BK; pB1 += BK;
    };

    int mi = lane >> 3, li = lane & 7;
    uint32_t arow[4], brow[2];
#pragma unroll
    for (int mt = 0; mt < 4; mt++)
        arow[mt] = (uint32_t)((wm * 64 + mt * 16 + (mi & 1) * 8 + li) * 64);
#pragma unroll
    for (int p = 0; p < 2; p++)
        brow[p] = (uint32_t)((wn * 32 + p * 16 + (mi & 1) * 8 + li) * 64);
    uint32_t kfr = (uint32_t)((mi >> 1) * 16);

    float acc[4][4][4];
#pragma unroll
    for (int a = 0; a < 4; a++)
#pragma unroll
        for (int b = 0; b < 4; b++)
#pragma unroll
            for (int r = 0; r < 4; r++) acc[a][b][r] = 0.f;

    int nchunk = K / BK;
    LOADS(0); CP_COMMIT();
    LOADS(1); CP_COMMIT();

    int cs = 0, ls = 2;
    for (int c = 0; c < nchunk; c++) {
        if (c + 2 < nchunk) {
            LOADS(ls); CP_COMMIT();
            if (++ls == NSTG) ls = 0;
            CP_WAIT2();
        } else if (c + 1 < nchunk) CP_WAIT1();
        else CP_WAIT0();
        __syncthreads();

        uint32_t sbase = sb + cs * S2_B;
        uint32_t bfh[4][2], bfl[4][2], afh[4], afl[4];
#pragma unroll
        for (int ks = 0; ks < 2; ks++) {
            uint32_t kb = kfr + ks * 32;
#pragma unroll
            for (int p = 0; p < 2; p++) {
                uint32_t r[4];
                ldsm4(r, sbase + 2 * T2_A + sw64(brow[p] + kb));
                bfh[2 * p][0] = r[0]; bfh[2 * p][1] = r[2];
                bfh[2 * p + 1][0] = r[1]; bfh[2 * p + 1][1] = r[3];
                ldsm4(r, sbase + 2 * T2_A + T2_B + sw64(brow[p] + kb));
                bfl[2 * p][0] = r[0]; bfl[2 * p][1] = r[2];
                bfl[2 * p + 1][0] = r[1]; bfl[2 * p + 1][1] = r[3];
            }
#pragma unroll
            for (int mt = 0; mt < 4; mt++) {
                ldsm4(afh, sbase + 0 * T2_A + sw64(arow[mt] + kb));
                ldsm4(afl, sbase + 1 * T2_A + sw64(arow[mt] + kb));
#pragma unroll
                for (int nt = 0; nt < 4; nt++) mma16816(acc[mt][nt], afh, bfh[nt]);
#pragma unroll
                for (int nt = 0; nt < 4; nt++) mma16816(acc[mt][nt], afh, bfl[nt]);
#pragma unroll
                for (int nt = 0; nt < 4; nt++) mma16816(acc[mt][nt], afl, bfh[nt]);
            }
        }
        if (++cs == NSTG) cs = 0;
        __syncthreads();
    }

    int g = lane >> 2, t4 = lane & 3;
#pragma unroll
    for (int mt = 0; mt < 4; mt++) {
#pragma unroll
        for (int half = 0; half < 2; half++) {
            int rowg = tileM * 128 + wm * 64 + mt * 16 + half * 8 + g;
            int orow = (rowg / seg_rows) * seg_stride + row_off + (rowg % seg_rows);
            size_t rbase = (size_t)orow * N + tileN * 256 + wn * 32;
            const float* brows = jbias ? (jbias + tileN * 256 + wn * 32) : nullptr;
#pragma unroll
            for (int nt = 0; nt < 4; nt++) {
                int col = nt * 8 + t4 * 2;
                float vx = acc[mt][nt][half * 2 + 0];
                float vy = acc[mt][nt][half * 2 + 1];
                if (brows) { vx += brows[col]; vy += brows[col + 1]; }
                if (jC) *(float2*)(jC + rbase + col) = make_float2(vx, vy);
                if (jCh) {
                    __nv_bfloat16 hx = __float2bfloat16(vx);
                    __nv_bfloat16 hy = __float2bfloat16(vy);
                    *(__nv_bfloat162*)(jCh + rbase + col) = __nv_bfloat162(hx, hy);
                    *(__nv_bfloat162*)(jCl + rbase + col) = __nv_bfloat162(
                        __float2bfloat16(vx - __bfloat162float(hx)),
                        __float2bfloat16(vy - __bfloat162float(hy)));
                }
            }
        }
    }
}

// ---- batched fp32 -> bf16 hi/lo split -------------------------------------
#define MAXS 9
struct SpBatch {
    int njobs;
    int prefix[MAXS + 1];
    const float* in[MAXS];
    __nv_bfloat16 *h[MAXS], *l[MAXS];
};
__global__ void split_k(SpBatch bat)
{
    int gi = blockIdx.x * blockDim.x + threadIdx.x;
    if (gi >= bat.prefix[bat.njobs]) return;
    int j = 0;
#pragma unroll
    for (int t = 1; t < MAXS; t++)
        if (t < bat.njobs && gi >= bat.prefix[t]) j = t;
    int i = gi - bat.prefix[j];
    const float* in = bat.in[j];
    float4 a = ((const float4*)in)[2 * i];
    float4 b = ((const float4*)in)[2 * i + 1];
    float v[8] = {a.x, a.y, a.z, a.w, b.x, b.y, b.z, b.w};
    union { __nv_bfloat162 h2[4]; uint4 u; } H, L;
#pragma unroll
    for (int t = 0; t < 4; t++) {
        __nv_bfloat16 h0 = __float2bfloat16(v[2 * t]);
        __nv_bfloat16 h1 = __float2bfloat16(v[2 * t + 1]);
        H.h2[t] = __nv_bfloat162(h0, h1);
        L.h2[t] = __nv_bfloat162(
            __float2bfloat16(v[2 * t] - __bfloat162float(h0)),
            __float2bfloat16(v[2 * t + 1] - __bfloat162float(h1)));
    }
    ((uint4*)bat.h[j])[i] = H.u;
    ((uint4*)bat.l[j])[i] = L.u;
}

// ---- batched fused transpose + split --------------------------------------
struct TsBatch {
    const float* in[4];
    __nv_bfloat16 *h[4], *l[4];
    int R[4], Cc[4];
};
__global__ void tsplit_k(TsBatch bat)
{
    int z = blockIdx.z;
    int R = bat.R[z], Cc = bat.Cc[z];
    int bx = blockIdx.x * 32, by = blockIdx.y * 32;
    if (bx >= Cc || by >= R) return;
    __shared__ float tile[32][33];
    int tx = threadIdx.x, ty = threadIdx.y;
    const float* in = bat.in[z];
#pragma unroll
    for (int jj = 0; jj < 4; jj++)
        tile[ty + 8 * jj][tx] = in[(size_t)(by + ty + 8 * jj) * Cc + bx + tx];
    __syncthreads();
#pragma unroll
    for (int jj = 0; jj < 4; jj++) {
        float v = tile[tx][ty + 8 * jj];
        __nv_bfloat16 hv = __float2bfloat16(v);
        size_t o = (size_t)(bx + ty + 8 * jj) * R + by + tx;
        bat.h[z][o] = hv;
        bat.l[z][o] = __float2bfloat16(v - __bfloat162float(hv));
    }
}

// ---- memory-net row norm -> bf16 h/l --------------------------------------
__global__ __launch_bounds__(128) void memnorm_k(
    const float* __restrict__ in, const float* __restrict__ g,
    const float* __restrict__ b, const float* __restrict__ add,
    __nv_bfloat16* __restrict__ oh, __nv_bfloat16* __restrict__ ol, int do_silu)
{
    int r = blockIdx.x, t = threadIdx.x;
    float v = in[(size_t)r * 128 + t];
    if (do_silu) v = v / (1.f + __expf(-v));
    __shared__ float ws[4];
    int w = t >> 5, l = t & 31;
    float s = v;
#pragma unroll
    for (int o = 16; o; o >>= 1) s += __shfl_xor_sync(0xffffffffu, s, o);
    if (l == 0) ws[w] = s;
    __syncthreads();
    float mu = (ws[0] + ws[1] + ws[2] + ws[3]) * (1.f / 128.f);
    __syncthreads();
    float d = v - mu;
    float s2 = d * d;
#pragma unroll
    for (int o = 16; o; o >>= 1) s2 += __shfl_xor_sync(0xffffffffu, s2, o);
    if (l == 0) ws[w] = s2;
    __syncthreads();
    float var = (ws[0] + ws[1] + ws[2] + ws[3]) * (1.f / 128.f);
    float y = d * rsqrtf(var + 1e-5f) * g[t] + b[t];
    if (add) y += add[t];
    __nv_bfloat16 hv = __float2bfloat16(y);
    oh[(size_t)r * 128 + t] = hv;
    ol[(size_t)r * 128 + t] = __float2bfloat16(y - __bfloat162float(hv));
}

// ---- LayerNorm(1024) -> bf16 h/l ------------------------------------------
__global__ __launch_bounds__(256) void ln1024_k(
    const float* __restrict__ in, const float* __restrict__ g,
    const float* __restrict__ b, __nv_bfloat16* __restrict__ oh,
    __nv_bfloat16* __restrict__ ol)
{
    int r = blockIdx.x, t = threadIdx.x;
    const float* row = in + (size_t)r * 1024;
    float4 v = *(const float4*)(row + t * 4);
    __shared__ float ws[8];
    int w = t >> 5, l = t & 31;
    float s = v.x + v.y + v.z + v.w;
#pragma unroll
    for (int o = 16; o; o >>= 1) s += __shfl_xor_sync(0xffffffffu, s, o);
    if (l == 0) ws[w] = s;
    __syncthreads();
    float mu = 0.f;
#pragma unroll
    for (int i = 0; i < 8; i++) mu += ws[i];
    mu *= (1.f / 1024.f);
    __syncthreads();
    float dx = v.x - mu, dy = v.y - mu, dz = v.z - mu, dw = v.w - mu;
    float s2 = dx * dx + dy * dy + dz * dz + dw * dw;
#pragma unroll
    for (int o = 16; o; o >>= 1) s2 += __shfl_xor_sync(0xffffffffu, s2, o);
    if (l == 0) ws[w] = s2;
    __syncthreads();
    float var = 0.f;
#pragma unroll
    for (int i = 0; i < 8; i++) var += ws[i];
    var *= (1.f / 1024.f);
    float inv = rsqrtf(var + 1e-5f);
    float4 gg = *(const float4*)(g + t * 4);
    float4 bb = *(const float4*)(b + t * 4);
    float y[4] = { dx * inv * gg.x + bb.x, dy * inv * gg.y + bb.y,
                   dz * inv * gg.z + bb.z, dw * inv * gg.w + bb.w };
    union { __nv_bfloat162 b2[2]; uint2 u; } H, L;
#pragma unroll
    for (int jj = 0; jj < 2; jj++) {
        __nv_bfloat16 h0 = __float2bfloat16(y[2 * jj]);
        __nv_bfloat16 h1 = __float2bfloat16(y[2 * jj + 1]);
        H.b2[jj] = __nv_bfloat162(h0, h1);
        L.b2[jj] = __nv_bfloat162(
            __float2bfloat16(y[2 * jj] - __bfloat162float(h0)),
            __float2bfloat16(y[2 * jj + 1] - __bfloat162float(h1)));
    }
    *(uint2*)(oh + (size_t)r * 1024 + t * 4) = H.u;
    *(uint2*)(ol + (size_t)r * 1024 + t * 4) = L.u;
}

// ---- persistent-memory k/v rows -------------------------------------------
__global__ void pmproj_k(const float* __restrict__ pm,
                         const float* __restrict__ K2, const float* __restrict__ V2,
                         const float* __restrict__ bk, const float* __restrict__ bv,
                         float* __restrict__ kpm, float* __restrict__ vpm)
{
    int i = blockIdx.x * blockDim.x + threadIdx.x;
    if (i >= 2 * PDIM * CDIM) return;
    int which = i >> 12;
    int p = (i >> 10) & 3;
    int n = i & 1023;
    const float* W = (which ? V2 : K2) + (size_t)n * 1024;
    const float* row = pm + p * 1024;
    float acc = which ? bv[n] : bk[n];
#pragma unroll 4
    for (int c = 0; c < 1024; c += 4) {
        float4 a = *(const float4*)(row + c);
        float4 w = *(const float4*)(W + c);
        acc += a.x * w.x + a.y * w.y + a.z * w.z + a.w * w.w;
    }
    (which ? vpm : kpm)[p * 1024 + n] = acc;
}

// ---- biases for retrieved k/v rows ----------------------------------------
__global__ void bias_ret_k(const float* __restrict__ K2, const float* __restrict__ V2,
                           const float* __restrict__ mob,
                           const float* __restrict__ bk, const float* __restrict__ bv,
                           float* __restrict__ ok, float* __restrict__ ov)
{
    int n = blockIdx.x * blockDim.x + threadIdx.x;
    if (n < 1024) {
        float a = bk[n];
        for (int c = 0; c < 1024; c++) a += K2[n * 1024 + c] * mob[c];
        ok[n] = a;
    } else if (n < 2048) {
        int m = n - 1024;
        float a = bv[m];
        for (int c = 0; c < 1024; c++) a += V2[m * 1024 + c] * mob[c];
        ov[m] = a;
    }
}

// ---- broadcast pm k/v into every segment ----------------------------------
__global__ void copy_pm_k(const float* __restrict__ kpm, const float* __restrict__ vpm,
                          float* __restrict__ kctx, float* __restrict__ vctx)
{
    int i = blockIdx.x * blockDim.x + threadIdx.x;
    if (i >= NSEG * PDIM * CDIM) return;
    int seg = i >> 12;
    int rem = i & 4095;
    size_t dst = ((size_t)seg * TCTX + SEGS) * CDIM + rem;
    kctx[dst] = kpm[rem];
    vctx[dst] = vpm[rem];
}

// ---- attention: register-tiled 4x4, all LDS.128 ---------------------------
#define ATTN_SMEM ((64*128 + 2*132*132 + 64*132) * 4)
__global__ __launch_bounds__(256) void attn_k(
    const float* __restrict__ q, const float* __restrict__ kc,
    const float* __restrict__ vc,
    __nv_bfloat16* __restrict__ oh, __nv_bfloat16* __restrict__ ol)
{
    extern __shared__ float smf[];
    float* qs = smf;
    float* ks = qs + 64 * 128;
    float* vs = ks + 132 * 132;
    float* ps = vs + 132 * 132;
    int h = blockIdx.x, seg = blockIdx.y;
    int tid = threadIdx.x;

    for (int i = tid; i < 64 * 32; i += 256) {
        int s = i >> 5, d4 = (i & 31) << 2;
        *(float4*)&qs[s * 128 + d4] =
            *(const float4*)(q + (size_t)(seg * SEGS + s) * CDIM + h * HD + d4);
    }
    for (int i = tid; i < 132 * 32; i += 256) {
        int t = i >> 5, d4 = (i & 31) << 2;
        *(float4*)&ks[t * 132 + d4] =
            *(const float4*)(kc + (size_t)(seg * TCTX + t) * CDIM + h * HD + d4);
        *(float4*)&vs[t * 132 + d4] =
            *(const float4*)(vc + (size_t)(seg * TCTX + t) * CDIM + h * HD + d4);
    }
    __syncthreads();

    const float scale = 0.08838834764831845f;
    for (int tile = tid; tile < 16 * 33; tile += 256) {
        int st = tile / 33, tt = tile - st * 33;
        int s0 = st * 4, t0 = tt * 4;
        float a[4][4];
#pragma unroll
        for (int i = 0; i < 4; i++)
#pragma unroll
            for (int jj = 0; jj < 4; jj++) a[i][jj] = 0.f;
        for (int d = 0; d < 128; d += 4) {
            float4 qv[4], kv[4];
#pragma unroll
            for (int i = 0; i < 4; i++) qv[i] = *(const float4*)&qs[(s0 + i) * 128 + d];
#pragma unroll
            for (int jj = 0; jj < 4; jj++) kv[jj] = *(const float4*)&ks[(t0 + jj) * 132 + d];
#pragma unroll
            for (int i = 0; i < 4; i++)
#pragma unroll
                for (int jj = 0; jj < 4; jj++)
                    a[i][jj] += qv[i].x * kv[jj].x + qv[i].y * kv[jj].y
                              + qv[i].z * kv[jj].z + qv[i].w * kv[jj].w;
        }
#pragma unroll
        for (int i = 0; i < 4; i++)
#pragma unroll
            for (int jj = 0; jj < 4; jj++)
                ps[(s0 + i) * 132 + t0 + jj] = a[i][jj] * scale;
    }
    __syncthreads();

    int w = tid >> 5, l = tid & 31;
    for (int s = w; s < 64; s += 8) {
        float* pr = ps + s * 132;
        float mx = -1e30f;
        for (int t = l; t < 132; t += 32) mx = fmaxf(mx, pr[t]);
#pragma unroll
        for (int o = 16; o; o >>= 1) mx = fmaxf(mx, __shfl_xor_sync(0xffffffffu, mx, o));
        float sum = 0.f;
        for (int t = l; t < 132; t += 32) {
            float e = __expf(pr[t] - mx);
            pr[t] = e;
            sum += e;
        }
#pragma unroll
        for (int o = 16; o; o >>= 1) sum += __shfl_xor_sync(0xffffffffu, sum, o);
        float inv = 1.f / sum;
        for (int t = l; t < 132; t += 32) pr[t] *= inv;
    }
    __syncthreads();

    for (int tile = tid; tile < 16 * 32; tile += 256) {
        int st = tile >> 5, dt = tile & 31;
        int s0 = st * 4, d0 = dt * 4;
        float4 acc[4];
#pragma unroll
        for (int i = 0; i < 4; i++) acc[i] = make_float4(0.f, 0.f, 0.f, 0.f);
        for (int t = 0; t < 132; t += 4) {
            float4 pv[4], vv[4];
#pragma unroll
            for (int i = 0; i < 4; i++) pv[i] = *(const float4*)&ps[(s0 + i) * 132 + t];
#pragma unroll
            for (int jj = 0; jj < 4; jj++) vv[jj] = *(const float4*)&vs[(t + jj) * 132 + d0];
#pragma unroll
            for (int i = 0; i < 4; i++) {
                acc[i].x += pv[i].x * vv[0].x + pv[i].y * vv[1].x + pv[i].z * vv[2].x + pv[i].w * vv[3].x;
                acc[i].y += pv[i].x * vv[0].y + pv[i].y * vv[1].y + pv[i].z * vv[2].y + pv[i].w * vv[3].y;
                acc[i].z += pv[i].x * vv[0].z + pv[i].y * vv[1].z + pv[i].z * vv[2].z + pv[i].w * vv[3].z;
                acc[i].w += pv[i].x * vv[0].w + pv[i].y * vv[1].w + pv[i].z * vv[2].w + pv[i].w * vv[3].w;
            }
        }
#pragma unroll
        for (int i = 0; i < 4; i++) {
            size_t o = (size_t)(seg * SEGS + s0 + i) * CDIM + h * HD + d0;
            float y[4] = {acc[i].x, acc[i].y, acc[i].z, acc[i].w};
            union { __nv_bfloat162 b2[2]; uint2 u; } H, L;
#pragma unroll
            for (int jj = 0; jj < 2; jj++) {
                __nv_bfloat16 h0 = __float2bfloat16(y[2 * jj]);
                __nv_bfloat16 h1 = __float2bfloat16(y[2 * jj + 1]);
                H.b2[jj] = __nv_bfloat162(h0, h1);
                L.b2[jj] = __nv_bfloat162(
                    __float2bfloat16(y[2 * jj] - __bfloat162float(h0)),
                    __float2bfloat16(y[2 * jj + 1] - __bfloat162float(h1)));
            }
            *(uint2*)(oh + o) = H.u;
            *(uint2*)(ol + o) = L.u;
        }
    }
}

// ---- z = sigmoid(gate)*attno + x  -> bf16 h/l -----------------------------
__global__ void combine_k(const float* __restrict__ gl, const float* __restrict__ ao,
                          const float* __restrict__ x,
                          __nv_bfloat16* __restrict__ zh, __nv_bfloat16* __restrict__ zl,
                          int n4)
{
    int i = blockIdx.x * blockDim.x + threadIdx.x;
    if (i >= n4) return;
    float4 gv = ((const float4*)gl)[i];
    float4 av = ((const float4*)ao)[i];
    float4 xv = ((const float4*)x)[i];
    float y[4];
    y[0] = av.x / (1.f + __expf(-gv.x)) + xv.x;
    y[1] = av.y / (1.f + __expf(-gv.y)) + xv.y;
    y[2] = av.z / (1.f + __expf(-gv.z)) + xv.z;
    y[3] = av.w / (1.f + __expf(-gv.w)) + xv.w;
    union { __nv_bfloat162 b2[2]; uint2 u; } H, L;
#pragma unroll
    for (int jj = 0; jj < 2; jj++) {
        __nv_bfloat16 h0 = __float2bfloat16(y[2 * jj]);
        __nv_bfloat16 h1 = __float2bfloat16(y[2 * jj + 1]);
        H.b2[jj] = __nv_bfloat162(h0, h1);
        L.b2[jj] = __nv_bfloat162(
            __float2bfloat16(y[2 * jj] - __bfloat162float(h0)),
            __float2bfloat16(y[2 * jj + 1] - __bfloat162float(h1)));
    }
    ((uint2*)zh)[i] = H.u;
    ((uint2*)zl)[i] = L.u;
}

// ---------------------------------------------------------------------------
extern "C" void kernel_launch(void* const* d_in, const int* in_sizes, int n_in,
                              void* d_out, int out_size)
{
    (void)in_sizes; (void)n_in; (void)out_size;
    const float* x        = (const float*)d_in[0];
    const float* pm       = (const float*)d_in[1];
    const float* Wq       = (const float*)d_in[2];
    const float* Wk       = (const float*)d_in[3];
    const float* Wv       = (const float*)d_in[4];
    const float* mem_W1   = (const float*)d_in[5];
    const float* mem_b1   = (const float*)d_in[6];
    const float* ln1_g    = (const float*)d_in[7];
    const float* ln1_b    = (const float*)d_in[8];
    const float* mem_W2   = (const float*)d_in[9];
    const float* mem_b2   = (const float*)d_in[10];
    const float* ln2_g    = (const float*)d_in[11];
    const float* ln2_b    = (const float*)d_in[12];
    const float* mem_outW = (const float*)d_in[13];
    const float* mem_outb = (const float*)d_in[14];
    const float* mstate   = (const float*)d_in[15];
    const float* mha_Wq   = (const float*)d_in[16];
    const float* mha_bq   = (const float*)d_in[17];
    const float* mha_Wk   = (const float*)d_in[18];
    const float* mha_bk   = (const float*)d_in[19];
    const float* mha_Wv   = (const float*)d_in[20];
    const float* mha_bv   = (const float*)d_in[21];
    const float* mha_Wo   = (const float*)d_in[22];
    const float* mha_bo   = (const float*)d_in[23];
    const float* gn_g     = (const float*)d_in[24];
    const float* gn_b     = (const float*)d_in[25];
    const float* gate_W   = (const float*)d_in[26];
    const float* gate_b   = (const float*)d_in[27];
    const float* out_W    = (const float*)d_in[28];
    const float* out_b    = (const float*)d_in[29];
    float* out = (float*)d_out;

    float *K2, *V2, *kpm, *vpm, *bkret, *bvret;
    float *mA, *qb, *kctx, *vctx, *attno, *gate;
    __nv_bfloat16 *xh, *xl, *sh, *sl, *mbh, *mbl;
    __nv_bfloat16 *q2h, *q2l, *k2h, *k2l, *v2h, *v2l, *amh, *aml;
    __nv_bfloat16 *kmh, *kml, *vmh, *vml, *woh, *wol, *gwh, *gwl, *owh, *owl;
    __nv_bfloat16 *mwqh, *mwql, *mwkh, *mwkl, *mwvh, *mwvl;
    __nv_bfloat16 *wqth, *wqtl, *wkth, *wktl, *wvth, *wvtl;
    __nv_bfloat16 *mw1h, *mw1l, *mowth, *mowtl, *w2h, *w2l;
    cudaGetSymbolAddress((void**)&K2, g_K2);
    cudaGetSymbolAddress((void**)&V2, g_V2);
    cudaGetSymbolAddress((void**)&kpm, g_kpm);
    cudaGetSymbolAddress((void**)&vpm, g_vpm);
    cudaGetSymbolAddress((void**)&bkret, g_bkret);
    cudaGetSymbolAddress((void**)&bvret, g_bvret);
    cudaGetSymbolAddress((void**)&mA, g_mA);
    cudaGetSymbolAddress((void**)&qb, g_qb);
    cudaGetSymbolAddress((void**)&kctx, g_kctx);
    cudaGetSymbolAddress((void**)&vctx, g_vctx);
    cudaGetSymbolAddress((void**)&attno, g_attno);
    cudaGetSymbolAddress((void**)&gate, g_gate);
    cudaGetSymbolAddress((void**)&xh, g_xh);   cudaGetSymbolAddress((void**)&xl, g_xl);
    cudaGetSymbolAddress((void**)&sh, g_sh);   cudaGetSymbolAddress((void**)&sl, g_sl);
    cudaGetSymbolAddress((void**)&mbh, g_mbh); cudaGetSymbolAddress((void**)&mbl, g_mbl);
    cudaGetSymbolAddress((void**)&q2h, g_q2h); cudaGetSymbolAddress((void**)&q2l, g_q2l);
    cudaGetSymbolAddress((void**)&k2h, g_k2h); cudaGetSymbolAddress((void**)&k2l, g_k2l);
    cudaGetSymbolAddress((void**)&v2h, g_v2h); cudaGetSymbolAddress((void**)&v2l, g_v2l);
    cudaGetSymbolAddress((void**)&amh, g_amh); cudaGetSymbolAddress((void**)&aml, g_aml);
    cudaGetSymbolAddress((void**)&kmh, g_kmh); cudaGetSymbolAddress((void**)&kml, g_kml);
    cudaGetSymbolAddress((void**)&vmh, g_vmh); cudaGetSymbolAddress((void**)&vml, g_vml);
    cudaGetSymbolAddress((void**)&woh, g_woh); cudaGetSymbolAddress((void**)&wol, g_wol);
    cudaGetSymbolAddress((void**)&gwh, g_gwh); cudaGetSymbolAddress((void**)&gwl, g_gwl);
    cudaGetSymbolAddress((void**)&owh, g_owh); cudaGetSymbolAddress((void**)&owl, g_owl);
    cudaGetSymbolAddress((void**)&mwqh, g_mwqh); cudaGetSymbolAddress((void**)&mwql, g_mwql);
    cudaGetSymbolAddress((void**)&mwkh, g_mwkh); cudaGetSymbolAddress((void**)&mwkl, g_mwkl);
    cudaGetSymbolAddress((void**)&mwvh, g_mwvh); cudaGetSymbolAddress((void**)&mwvl, g_mwvl);
    cudaGetSymbolAddress((void**)&wqth, g_wqth); cudaGetSymbolAddress((void**)&wqtl, g_wqtl);
    cudaGetSymbolAddress((void**)&wkth, g_wkth); cudaGetSymbolAddress((void**)&wktl, g_wktl);
    cudaGetSymbolAddress((void**)&wvth, g_wvth); cudaGetSymbolAddress((void**)&wvtl, g_wvtl);
    cudaGetSymbolAddress((void**)&mw1h, g_mw1h); cudaGetSymbolAddress((void**)&mw1l, g_mw1l);
    cudaGetSymbolAddress((void**)&mowth, g_mowth); cudaGetSymbolAddress((void**)&mowtl, g_mowtl);
    cudaGetSymbolAddress((void**)&w2h, g_w2h); cudaGetSymbolAddress((void**)&w2l, g_w2l);

    static bool attr_done = false;
    if (!attr_done) {
        cudaFuncSetAttribute(attn_k, cudaFuncAttributeMaxDynamicSharedMemorySize, ATTN_SMEM);
        cudaFuncSetAttribute(tmma_k, cudaFuncAttributeMaxDynamicSharedMemorySize, TM_SMEM);
        cudaFuncSetAttribute(tmma256_k, cudaFuncAttributeMaxDynamicSharedMemorySize, TM2_SMEM);
        attr_done = true;
    }

    const int BIG = 1 << 30;

    TgBatch tb;
    auto tb_reset = [&]() { tb.njobs = 0; tb.prefix[0] = 0; };
    auto tb_add = [&](const __nv_bfloat16* ah, const __nv_bfloat16* al,
                      const __nv_bfloat16* bh, const __nv_bfloat16* bl,
                      const float* bias, float* C, __nv_bfloat16* Ch, __nv_bfloat16* Cl,
                      int M, int N, int K, int sr, int ss, int ro, int bn) {
        int j = tb.njobs++;
        tb.tilesN[j] = N / bn;
        tb.prefix[j + 1] = tb.prefix[j] + (M / 128) * (N / bn);
        tb.Ah[j] = ah; tb.Al[j] = al; tb.Bh[j] = bh; tb.Bl[j] = bl;
        tb.bias[j] = bias; tb.C[j] = C; tb.Ch[j] = Ch; tb.Cl[j] = Cl;
        tb.K[j] = K; tb.N[j] = N; tb.sr[j] = sr; tb.ss[j] = ss; tb.ro[j] = ro;
    };
    auto tb_go128 = [&]() { tmma_k<<<tb.prefix[tb.njobs], 256, TM_SMEM>>>(tb); };
    auto tb_go256 = [&]() { tmma256_k<<<tb.prefix[tb.njobs], 512, TM2_SMEM>>>(tb); };

    // ---- L0: all plain splits in ONE launch ----
    SpBatch sp; sp.njobs = 0; sp.prefix[0] = 0;
    auto sp_add = [&](const float* in, __nv_bfloat16* h, __nv_bfloat16* l, int n) {
        int j = sp.njobs++;
        sp.prefix[j + 1] = sp.prefix[j] + n / 8;
        sp.in[j] = in; sp.h[j] = h; sp.l[j] = l;
    };
    sp_add(x, xh, xl, NROWS * CDIM);
    sp_add(mha_Wq, mwqh, mwql, CDIM * CDIM);
    sp_add(mha_Wk, mwkh, mwkl, CDIM * CDIM);
    sp_add(mha_Wv, mwvh, mwvl, CDIM * CDIM);
    sp_add(mem_W1, mw1h, mw1l, MDIM * CDIM);
    sp_add(mem_W2, w2h, w2l, MDIM * MDIM);
    sp_add(mha_Wo, woh, wol, CDIM * CDIM);
    sp_add(gate_W, gwh, gwl, CDIM * CDIM);
    sp_add(out_W, owh, owl, CDIM * CDIM);
    split_k<<<(sp.prefix[sp.njobs] + 255) / 256, 256>>>(sp);

    // ---- L1: all transpose+splits in ONE launch ----
    TsBatch ts;
    ts.in[0] = Wq; ts.h[0] = wqth; ts.l[0] = wqtl; ts.R[0] = 1024; ts.Cc[0] = 1024;
    ts.in[1] = Wk; ts.h[1] = wkth; ts.l[1] = wktl; ts.R[1] = 1024; ts.Cc[1] = 1024;
    ts.in[2] = Wv; ts.h[2] = wvth; ts.l[2] = wvtl; ts.R[2] = 1024; ts.Cc[2] = 1024;
    ts.in[3] = mem_outW; ts.h[3] = mowth; ts.l[3] = mowtl; ts.R[3] = 1024; ts.Cc[3] = 128;
    tsplit_k<<<dim3(32, 32, 4), dim3(32, 8)>>>(ts);

    // ---- L2: batch {Q2, K2, V2, Amat} (N=1024 -> 256-wide kernel) ----
    tb_reset();
    tb_add(mwqh, mwql, wqth, wqtl, nullptr, nullptr, q2h, q2l, 1024, 1024, 1024, BIG, 0, 0, 256);
    tb_add(mwkh, mwkl, wkth, wktl, nullptr, K2, k2h, k2l, 1024, 1024, 1024, BIG, 0, 0, 256);
    tb_add(mwvh, mwvl, wvth, wvtl, nullptr, V2, v2h, v2l, 1024, 1024, 1024, BIG, 0, 0, 256);
    tb_add(mw1h, mw1l, wqth, wqtl, nullptr, nullptr, amh, aml, 128, 1024, 1024, BIG, 0, 0, 256);
    tb_go256();

    // ---- L3: batch {KM, VM, memnet1} (N=128 -> 128-wide kernel) ----
    tb_reset();
    tb_add(k2h, k2l, mowth, mowtl, nullptr, nullptr, kmh, kml, 1024, 128, 1024, BIG, 0, 0, 128);
    tb_add(v2h, v2l, mowth, mowtl, nullptr, nullptr, vmh, vml, 1024, 128, 1024, BIG, 0, 0, 128);
    tb_add(xh, xl, amh, aml, mem_b1, mA, nullptr, nullptr, NROWS, 128, 1024, BIG, 0, 0, 128);
    tb_go128();

    // ---- memnorm1 ----
    memnorm_k<<<NROWS, 128>>>(mA, ln1_g, ln1_b, nullptr, sh, sl, 1);

    // ---- L5: batch {q-proj, k-proj, v-proj} (N=1024) ----
    tb_reset();
    tb_add(xh, xl, q2h, q2l, mha_bq, qb, nullptr, nullptr, NROWS, 1024, 1024, BIG, 0, 0, 256);
    tb_add(xh, xl, k2h, k2l, mha_bk, kctx, nullptr, nullptr, NROWS, 1024, 1024, SEGS, TCTX, SEGS + PDIM, 256);
    tb_add(xh, xl, v2h, v2l, mha_bv, vctx, nullptr, nullptr, NROWS, 1024, 1024, SEGS, TCTX, SEGS + PDIM, 256);
    tb_go256();

    // ---- memory net part 2 (N=128) ----
    tb_reset();
    tb_add(sh, sl, w2h, w2l, mem_b2, mA, nullptr, nullptr, NROWS, 128, 128, BIG, 0, 0, 128);
    tb_go128();
    memnorm_k<<<NROWS, 128>>>(mA, ln2_g, ln2_b, mstate, mbh, mbl, 0);

    pmproj_k<<<32, 256>>>(pm, K2, V2, mha_bk, mha_bv, kpm, vpm);
    bias_ret_k<<<8, 256>>>(K2, V2, mem_outb, mha_bk, mha_bv, bkret, bvret);

    // ---- batch {k-ret, v-ret} (N=1024, K=128) ----
    tb_reset();
    tb_add(mbh, mbl, kmh, kml, bkret, kctx, nullptr, nullptr, NROWS, 1024, 128, SEGS, TCTX, 0, 256);
    tb_add(mbh, mbl, vmh, vml, bvret, vctx, nullptr, nullptr, NROWS, 1024, 128, SEGS, TCTX, 0, 256);
    tb_go256();

    copy_pm_k<<<(NSEG * PDIM * CDIM + 255) / 256, 256>>>(kpm, vpm, kctx, vctx);

    // ---- attention -> bf16 h/l directly ----
    attn_k<<<dim3(HEADS, NSEG), 256, ATTN_SMEM>>>(qb, kctx, vctx, sh, sl);

    // ---- output projection, gate, final (N=1024) ----
    tb_reset();
    tb_add(sh, sl, woh, wol, mha_bo, attno, nullptr, nullptr, NROWS, 1024, 1024, BIG, 0, 0, 256);
    tb_go256();
    ln1024_k<<<NROWS, 256>>>(attno, gn_g, gn_b, sh, sl);
    tb_reset();
    tb_add(sh, sl, gwh, gwl, gate_b, gate, nullptr, nullptr, NROWS, 1024, 1024, BIG, 0, 0, 256);
    tb_go256();
    combine_k<<<(NROWS * CDIM / 4 + 255) / 256, 256>>>(gate, attno, x, sh, sl, NROWS * CDIM / 4);
    tb_reset();
    tb_add(sh, sl, owh, owl, out_b, out, nullptr, nullptr, NROWS, 1024, 1024, BIG, 0, 0, 256);
    tb_go256();
}

// round 10
// speedup vs baseline: 1.1374x; 1.1374x over previous
#include <cuda_runtime.h>
#include <cuda_bf16.h>
#include <cstdint>

// Problem constants
#define NROWS 16384      // B*L
#define CDIM  1024
#define MDIM  128
#define NSEG  256
#define SEGS  64
#define TCTX  132
#define PDIM  4
#define HEADS 8
#define HD    128

// ===================== helpers (base sm_103 PTX only) ======================
__device__ __forceinline__ uint32_t smem_u32(const void* p) {
    uint32_t a;
    asm("{ .reg .u64 t; cvta.to.shared.u64 t, %1; cvt.u32.u64 %0, t; }" : "=r"(a) : "l"(p));
    return a;
}
__device__ __forceinline__ void ldsm4(uint32_t* r, uint32_t a) {
    asm volatile("ldmatrix.sync.aligned.m8n8.x4.shared.b16 {%0,%1,%2,%3}, [%4];"
        : "=r"(r[0]), "=r"(r[1]), "=r"(r[2]), "=r"(r[3]) : "r"(a));
}
__device__ __forceinline__ void mma16816(float* c, const uint32_t* a, const uint32_t* b) {
    asm volatile(
        "mma.sync.aligned.m16n8k16.row.col.f32.bf16.bf16.f32 "
        "{%0,%1,%2,%3}, {%4,%5,%6,%7}, {%8,%9}, {%0,%1,%2,%3};"
        : "+f"(c[0]), "+f"(c[1]), "+f"(c[2]), "+f"(c[3])
        : "r"(a[0]), "r"(a[1]), "r"(a[2]), "r"(a[3]), "r"(b[0]), "r"(b[1]));
}
__device__ __forceinline__ void cpasync16(uint32_t dst, const void* src) {
    asm volatile("cp.async.cg.shared.global [%0], [%1], 16;" :: "r"(dst), "l"(src));
}
#define CP_COMMIT() asm volatile("cp.async.commit_group;" ::: "memory")
#define CP_WAIT2()  asm volatile("cp.async.wait_group 2;" ::: "memory")
#define CP_WAIT1()  asm volatile("cp.async.wait_group 1;" ::: "memory")
#define CP_WAIT0()  asm volatile("cp.async.wait_group 0;" ::: "memory")

// ---------------- scratch (device globals) ---------------------------------
__device__ float g_K2[CDIM*CDIM];
__device__ float g_V2[CDIM*CDIM];
__device__ float g_kpm[PDIM*CDIM];
__device__ float g_vpm[PDIM*CDIM];
__device__ float g_bkret[CDIM];
__device__ float g_bvret[CDIM];
__device__ float g_mA[NROWS*MDIM];
__device__ float g_qb[NROWS*CDIM];
__device__ float g_kctx[NSEG*TCTX*CDIM];
__device__ float g_vctx[NSEG*TCTX*CDIM];
__device__ float g_attno[NROWS*CDIM];
__device__ float g_gate[NROWS*CDIM];
// bf16 hi/lo
__device__ __nv_bfloat16 g_xh[NROWS*CDIM],  g_xl[NROWS*CDIM];
__device__ __nv_bfloat16 g_sh[NROWS*CDIM],  g_sl[NROWS*CDIM];
__device__ __nv_bfloat16 g_mbh[NROWS*MDIM], g_mbl[NROWS*MDIM];
__device__ __nv_bfloat16 g_q2h[CDIM*CDIM],  g_q2l[CDIM*CDIM];
__device__ __nv_bfloat16 g_k2h[CDIM*CDIM],  g_k2l[CDIM*CDIM];
__device__ __nv_bfloat16 g_v2h[CDIM*CDIM],  g_v2l[CDIM*CDIM];
__device__ __nv_bfloat16 g_amh[MDIM*CDIM],  g_aml[MDIM*CDIM];
__device__ __nv_bfloat16 g_kmh[CDIM*MDIM],  g_kml[CDIM*MDIM];
__device__ __nv_bfloat16 g_vmh[CDIM*MDIM],  g_vml[CDIM*MDIM];
__device__ __nv_bfloat16 g_woh[CDIM*CDIM],  g_wol[CDIM*CDIM];
__device__ __nv_bfloat16 g_gwh[CDIM*CDIM],  g_gwl[CDIM*CDIM];
__device__ __nv_bfloat16 g_owh[CDIM*CDIM],  g_owl[CDIM*CDIM];
__device__ __nv_bfloat16 g_mwqh[CDIM*CDIM], g_mwql[CDIM*CDIM];
__device__ __nv_bfloat16 g_mwkh[CDIM*CDIM], g_mwkl[CDIM*CDIM];
__device__ __nv_bfloat16 g_mwvh[CDIM*CDIM], g_mwvl[CDIM*CDIM];
__device__ __nv_bfloat16 g_wqth[CDIM*CDIM], g_wqtl[CDIM*CDIM];
__device__ __nv_bfloat16 g_wkth[CDIM*CDIM], g_wktl[CDIM*CDIM];
__device__ __nv_bfloat16 g_wvth[CDIM*CDIM], g_wvtl[CDIM*CDIM];
__device__ __nv_bfloat16 g_mw1h[MDIM*CDIM], g_mw1l[MDIM*CDIM];
__device__ __nv_bfloat16 g_mowth[MDIM*CDIM], g_mowtl[MDIM*CDIM];
__device__ __nv_bfloat16 g_w2h[MDIM*MDIM],  g_w2l[MDIM*MDIM];

__device__ __forceinline__ uint32_t sw64(uint32_t b) { return b ^ ((b >> 3) & 0x30); }

// ============ batched HMMA bf16x3 GEMM, cp.async 3-stage pipeline ==========
#define BK 32
#define TILE_B (128*BK*2)          // 8192 bytes per tile
#define STG_B  (4*TILE_B)          // 32768 per stage
#define NSTG   3
#define TM_SMEM (NSTG*STG_B)       // 98304
#define MAXJ 8

struct TgBatch {
    int njobs;
    int prefix[MAXJ + 1];
    int tilesN[MAXJ];
    const __nv_bfloat16 *Ah[MAXJ], *Al[MAXJ], *Bh[MAXJ], *Bl[MAXJ];
    const float* bias[MAXJ];
    float* C[MAXJ];
    __nv_bfloat16 *Ch[MAXJ], *Cl[MAXJ];
    int K[MAXJ], N[MAXJ], sr[MAXJ], ss[MAXJ], ro[MAXJ];
};

__global__ __launch_bounds__(256, 2) void tmma_k(TgBatch bat)
{
    extern __shared__ char sm[];
    uint32_t sb = smem_u32(sm);
    int tid = threadIdx.x, wid = tid >> 5, lane = tid & 31;

    int bt = blockIdx.x;
    int j = 0;
#pragma unroll
    for (int t = 1; t < MAXJ; t++)
        if (t < bat.njobs && bt >= bat.prefix[t]) j = t;
    int local = bt - bat.prefix[j];
    int tN = bat.tilesN[j];
    int tileN = local % tN;
    int tileM = local / tN;

    const __nv_bfloat16* jAh = bat.Ah[j];
    const __nv_bfloat16* jAl = bat.Al[j];
    const __nv_bfloat16* jBh = bat.Bh[j];
    const __nv_bfloat16* jBl = bat.Bl[j];
    const float* jbias = bat.bias[j];
    float* jC = bat.C[j];
    __nv_bfloat16* jCh = bat.Ch[j];
    __nv_bfloat16* jCl = bat.Cl[j];
    int K = bat.K[j], N = bat.N[j];
    int seg_rows = bat.sr[j], seg_stride = bat.ss[j], row_off = bat.ro[j];

    int wm = wid & 1, wn = wid >> 1;

    int row_ld = tid >> 2, c16 = tid & 3;
    int row_ld1 = (tid + 256) >> 2, c161 = (tid + 256) & 3;
    uint32_t dst_sw0 = sw64((uint32_t)(row_ld * 64 + c16 * 16));
    uint32_t dst_sw1 = sw64((uint32_t)(row_ld1 * 64 + c161 * 16));

    const __nv_bfloat16* p0[4];
    ptrdiff_t pdel = (ptrdiff_t)(row_ld1 - row_ld) * K + (ptrdiff_t)(c161 - c16) * 8;
    {
        const __nv_bfloat16* base[4] = {
            jAh + (size_t)tileM * 128 * K, jAl + (size_t)tileM * 128 * K,
            jBh + (size_t)tileN * 128 * K, jBl + (size_t)tileN * 128 * K };
#pragma unroll
        for (int t = 0; t < 4; t++)
            p0[t] = base[t] + (size_t)row_ld * K + c16 * 8;
    }
    auto LOADS = [&](int stage) {
        uint32_t sbase = sb + stage * STG_B;
#pragma unroll
        for (int t = 0; t < 4; t++) {
            cpasync16(sbase + t * TILE_B + dst_sw0, p0[t]);
            cpasync16(sbase + t * TILE_B + dst_sw1, p0[t] + pdel);
            p0[t] += BK;
        }
    };

    int mi = lane >> 3, li = lane & 7;
    uint32_t arow[4], brow[2];
#pragma unroll
    for (int mt = 0; mt < 4; mt++)
        arow[mt] = (uint32_t)((wm * 64 + mt * 16 + (mi & 1) * 8 + li) * 64);
#pragma unroll
    for (int p = 0; p < 2; p++)
        brow[p] = (uint32_t)((wn * 32 + p * 16 + (mi & 1) * 8 + li) * 64);
    uint32_t kfr = (uint32_t)((mi >> 1) * 16);

    float acc[4][4][4];
#pragma unroll
    for (int a = 0; a < 4; a++)
#pragma unroll
        for (int b = 0; b < 4; b++)
#pragma unroll
            for (int r = 0; r < 4; r++) acc[a][b][r] = 0.f;

    int nchunk = K / BK;
    LOADS(0); CP_COMMIT();
    LOADS(1); CP_COMMIT();

    int cs = 0, ls = 2;
    for (int c = 0; c < nchunk; c++) {
        if (c + 2 < nchunk) {
            LOADS(ls); CP_COMMIT();
            if (++ls == NSTG) ls = 0;
            CP_WAIT2();
        } else if (c + 1 < nchunk) CP_WAIT1();
        else CP_WAIT0();
        __syncthreads();

        uint32_t sbase = sb + cs * STG_B;
        uint32_t bfh[4][2], bfl[4][2], afh[4], afl[4];
#pragma unroll
        for (int ks = 0; ks < 2; ks++) {
            uint32_t kb = kfr + ks * 32;
#pragma unroll
            for (int p = 0; p < 2; p++) {
                uint32_t r[4];
                ldsm4(r, sbase + 2 * TILE_B + sw64(brow[p] + kb));
                bfh[2 * p][0] = r[0]; bfh[2 * p][1] = r[2];
                bfh[2 * p + 1][0] = r[1]; bfh[2 * p + 1][1] = r[3];
                ldsm4(r, sbase + 3 * TILE_B + sw64(brow[p] + kb));
                bfl[2 * p][0] = r[0]; bfl[2 * p][1] = r[2];
                bfl[2 * p + 1][0] = r[1]; bfl[2 * p + 1][1] = r[3];
            }
#pragma unroll
            for (int mt = 0; mt < 4; mt++) {
                ldsm4(afh, sbase + 0 * TILE_B + sw64(arow[mt] + kb));
                ldsm4(afl, sbase + 1 * TILE_B + sw64(arow[mt] + kb));
#pragma unroll
                for (int nt = 0; nt < 4; nt++) mma16816(acc[mt][nt], afh, bfh[nt]);
#pragma unroll
                for (int nt = 0; nt < 4; nt++) mma16816(acc[mt][nt], afh, bfl[nt]);
#pragma unroll
                for (int nt = 0; nt < 4; nt++) mma16816(acc[mt][nt], afl, bfh[nt]);
            }
        }
        if (++cs == NSTG) cs = 0;
        __syncthreads();
    }

    // epilogue
    int g = lane >> 2, t4 = lane & 3;
#pragma unroll
    for (int mt = 0; mt < 4; mt++) {
#pragma unroll
        for (int half = 0; half < 2; half++) {
            int rowg = tileM * 128 + wm * 64 + mt * 16 + half * 8 + g;
            int orow = (rowg / seg_rows) * seg_stride + row_off + (rowg % seg_rows);
            size_t rbase = (size_t)orow * N + tileN * 128 + wn * 32;
            const float* brows = jbias ? (jbias + tileN * 128 + wn * 32) : nullptr;
#pragma unroll
            for (int nt = 0; nt < 4; nt++) {
                int col = nt * 8 + t4 * 2;
                float vx = acc[mt][nt][half * 2 + 0];
                float vy = acc[mt][nt][half * 2 + 1];
                if (brows) { vx += brows[col]; vy += brows[col + 1]; }
                if (jC) *(float2*)(jC + rbase + col) = make_float2(vx, vy);
                if (jCh) {
                    __nv_bfloat16 hx = __float2bfloat16(vx);
                    __nv_bfloat16 hy = __float2bfloat16(vy);
                    *(__nv_bfloat162*)(jCh + rbase + col) = __nv_bfloat162(hx, hy);
                    *(__nv_bfloat162*)(jCl + rbase + col) = __nv_bfloat162(
                        __float2bfloat16(vx - __bfloat162float(hx)),
                        __float2bfloat16(vy - __bfloat162float(hy)));
                }
            }
        }
    }
}

// ---- batched fp32 -> bf16 hi/lo split -------------------------------------
#define MAXS 9
struct SpBatch {
    int njobs;
    int prefix[MAXS + 1];
    const float* in[MAXS];
    __nv_bfloat16 *h[MAXS], *l[MAXS];
};
__global__ void split_k(SpBatch bat)
{
    int gi = blockIdx.x * blockDim.x + threadIdx.x;
    if (gi >= bat.prefix[bat.njobs]) return;
    int j = 0;
#pragma unroll
    for (int t = 1; t < MAXS; t++)
        if (t < bat.njobs && gi >= bat.prefix[t]) j = t;
    int i = gi - bat.prefix[j];
    const float* in = bat.in[j];
    float4 a = ((const float4*)in)[2 * i];
    float4 b = ((const float4*)in)[2 * i + 1];
    float v[8] = {a.x, a.y, a.z, a.w, b.x, b.y, b.z, b.w};
    union { __nv_bfloat162 h2[4]; uint4 u; } H, L;
#pragma unroll
    for (int t = 0; t < 4; t++) {
        __nv_bfloat16 h0 = __float2bfloat16(v[2 * t]);
        __nv_bfloat16 h1 = __float2bfloat16(v[2 * t + 1]);
        H.h2[t] = __nv_bfloat162(h0, h1);
        L.h2[t] = __nv_bfloat162(
            __float2bfloat16(v[2 * t] - __bfloat162float(h0)),
            __float2bfloat16(v[2 * t + 1] - __bfloat162float(h1)));
    }
    ((uint4*)bat.h[j])[i] = H.u;
    ((uint4*)bat.l[j])[i] = L.u;
}

// ---- batched fused transpose + split --------------------------------------
struct TsBatch {
    const float* in[4];
    __nv_bfloat16 *h[4], *l[4];
    int R[4], Cc[4];
};
__global__ void tsplit_k(TsBatch bat)
{
    int z = blockIdx.z;
    int R = bat.R[z], Cc = bat.Cc[z];
    int bx = blockIdx.x * 32, by = blockIdx.y * 32;
    if (bx >= Cc || by >= R) return;
    __shared__ float tile[32][33];
    int tx = threadIdx.x, ty = threadIdx.y;
    const float* in = bat.in[z];
#pragma unroll
    for (int jj = 0; jj < 4; jj++)
        tile[ty + 8 * jj][tx] = in[(size_t)(by + ty + 8 * jj) * Cc + bx + tx];
    __syncthreads();
#pragma unroll
    for (int jj = 0; jj < 4; jj++) {
        float v = tile[tx][ty + 8 * jj];
        __nv_bfloat16 hv = __float2bfloat16(v);
        size_t o = (size_t)(bx + ty + 8 * jj) * R + by + tx;
        bat.h[z][o] = hv;
        bat.l[z][o] = __float2bfloat16(v - __bfloat162float(hv));
    }
}

// ---- memory-net row norm -> bf16 h/l --------------------------------------
__global__ __launch_bounds__(128) void memnorm_k(
    const float* __restrict__ in, const float* __restrict__ g,
    const float* __restrict__ b, const float* __restrict__ add,
    __nv_bfloat16* __restrict__ oh, __nv_bfloat16* __restrict__ ol, int do_silu)
{
    int r = blockIdx.x, t = threadIdx.x;
    float v = in[(size_t)r * 128 + t];
    if (do_silu) v = v / (1.f + __expf(-v));
    __shared__ float ws[4];
    int w = t >> 5, l = t & 31;
    float s = v;
#pragma unroll
    for (int o = 16; o; o >>= 1) s += __shfl_xor_sync(0xffffffffu, s, o);
    if (l == 0) ws[w] = s;
    __syncthreads();
    float mu = (ws[0] + ws[1] + ws[2] + ws[3]) * (1.f / 128.f);
    __syncthreads();
    float d = v - mu;
    float s2 = d * d;
#pragma unroll
    for (int o = 16; o; o >>= 1) s2 += __shfl_xor_sync(0xffffffffu, s2, o);
    if (l == 0) ws[w] = s2;
    __syncthreads();
    float var = (ws[0] + ws[1] + ws[2] + ws[3]) * (1.f / 128.f);
    float y = d * rsqrtf(var + 1e-5f) * g[t] + b[t];
    if (add) y += add[t];
    __nv_bfloat16 hv = __float2bfloat16(y);
    oh[(size_t)r * 128 + t] = hv;
    ol[(size_t)r * 128 + t] = __float2bfloat16(y - __bfloat162float(hv));
}

// ---- LayerNorm(1024) -> bf16 h/l ------------------------------------------
__global__ __launch_bounds__(256) void ln1024_k(
    const float* __restrict__ in, const float* __restrict__ g,
    const float* __restrict__ b, __nv_bfloat16* __restrict__ oh,
    __nv_bfloat16* __restrict__ ol)
{
    int r = blockIdx.x, t = threadIdx.x;
    const float* row = in + (size_t)r * 1024;
    float4 v = *(const float4*)(row + t * 4);
    __shared__ float ws[8];
    int w = t >> 5, l = t & 31;
    float s = v.x + v.y + v.z + v.w;
#pragma unroll
    for (int o = 16; o; o >>= 1) s += __shfl_xor_sync(0xffffffffu, s, o);
    if (l == 0) ws[w] = s;
    __syncthreads();
    float mu = 0.f;
#pragma unroll
    for (int i = 0; i < 8; i++) mu += ws[i];
    mu *= (1.f / 1024.f);
    __syncthreads();
    float dx = v.x - mu, dy = v.y - mu, dz = v.z - mu, dw = v.w - mu;
    float s2 = dx * dx + dy * dy + dz * dz + dw * dw;
#pragma unroll
    for (int o = 16; o; o >>= 1) s2 += __shfl_xor_sync(0xffffffffu, s2, o);
    if (l == 0) ws[w] = s2;
    __syncthreads();
    float var = 0.f;
#pragma unroll
    for (int i = 0; i < 8; i++) var += ws[i];
    var *= (1.f / 1024.f);
    float inv = rsqrtf(var + 1e-5f);
    float4 gg = *(const float4*)(g + t * 4);
    float4 bb = *(const float4*)(b + t * 4);
    float y[4] = { dx * inv * gg.x + bb.x, dy * inv * gg.y + bb.y,
                   dz * inv * gg.z + bb.z, dw * inv * gg.w + bb.w };
    union { __nv_bfloat162 b2[2]; uint2 u; } H, L;
#pragma unroll
    for (int jj = 0; jj < 2; jj++) {
        __nv_bfloat16 h0 = __float2bfloat16(y[2 * jj]);
        __nv_bfloat16 h1 = __float2bfloat16(y[2 * jj + 1]);
        H.b2[jj] = __nv_bfloat162(h0, h1);
        L.b2[jj] = __nv_bfloat162(
            __float2bfloat16(y[2 * jj] - __bfloat162float(h0)),
            __float2bfloat16(y[2 * jj + 1] - __bfloat162float(h1)));
    }
    *(uint2*)(oh + (size_t)r * 1024 + t * 4) = H.u;
    *(uint2*)(ol + (size_t)r * 1024 + t * 4) = L.u;
}

// ---- persistent-memory k/v rows -------------------------------------------
__global__ void pmproj_k(const float* __restrict__ pm,
                         const float* __restrict__ K2, const float* __restrict__ V2,
                         const float* __restrict__ bk, const float* __restrict__ bv,
                         float* __restrict__ kpm, float* __restrict__ vpm)
{
    int i = blockIdx.x * blockDim.x + threadIdx.x;
    if (i >= 2 * PDIM * CDIM) return;
    int which = i >> 12;
    int p = (i >> 10) & 3;
    int n = i & 1023;
    const float* W = (which ? V2 : K2) + (size_t)n * 1024;
    const float* row = pm + p * 1024;
    float acc = which ? bv[n] : bk[n];
#pragma unroll 4
    for (int c = 0; c < 1024; c += 4) {
        float4 a = *(const float4*)(row + c);
        float4 w = *(const float4*)(W + c);
        acc += a.x * w.x + a.y * w.y + a.z * w.z + a.w * w.w;
    }
    (which ? vpm : kpm)[p * 1024 + n] = acc;
}

// ---- biases for retrieved k/v rows ----------------------------------------
__global__ void bias_ret_k(const float* __restrict__ K2, const float* __restrict__ V2,
                           const float* __restrict__ mob,
                           const float* __restrict__ bk, const float* __restrict__ bv,
                           float* __restrict__ ok, float* __restrict__ ov)
{
    int n = blockIdx.x * blockDim.x + threadIdx.x;
    if (n < 1024) {
        float a = bk[n];
        for (int c = 0; c < 1024; c++) a += K2[n * 1024 + c] * mob[c];
        ok[n] = a;
    } else if (n < 2048) {
        int m = n - 1024;
        float a = bv[m];
        for (int c = 0; c < 1024; c++) a += V2[m * 1024 + c] * mob[c];
        ov[m] = a;
    }
}

// ---- broadcast pm k/v into every segment ----------------------------------
__global__ void copy_pm_k(const float* __restrict__ kpm, const float* __restrict__ vpm,
                          float* __restrict__ kctx, float* __restrict__ vctx)
{
    int i = blockIdx.x * blockDim.x + threadIdx.x;
    if (i >= NSEG * PDIM * CDIM) return;
    int seg = i >> 12;
    int rem = i & 4095;
    size_t dst = ((size_t)seg * TCTX + SEGS) * CDIM + rem;
    kctx[dst] = kpm[rem];
    vctx[dst] = vpm[rem];
}

// ---- attention: register-tiled 4x4, all LDS.128 ---------------------------
#define ATTN_SMEM ((64*128 + 2*132*132 + 64*132) * 4)
__global__ __launch_bounds__(256) void attn_k(
    const float* __restrict__ q, const float* __restrict__ kc,
    const float* __restrict__ vc,
    __nv_bfloat16* __restrict__ oh, __nv_bfloat16* __restrict__ ol)
{
    extern __shared__ float smf[];
    float* qs = smf;
    float* ks = qs + 64 * 128;
    float* vs = ks + 132 * 132;
    float* ps = vs + 132 * 132;
    int h = blockIdx.x, seg = blockIdx.y;
    int tid = threadIdx.x;

    for (int i = tid; i < 64 * 32; i += 256) {
        int s = i >> 5, d4 = (i & 31) << 2;
        *(float4*)&qs[s * 128 + d4] =
            *(const float4*)(q + (size_t)(seg * SEGS + s) * CDIM + h * HD + d4);
    }
    for (int i = tid; i < 132 * 32; i += 256) {
        int t = i >> 5, d4 = (i & 31) << 2;
        *(float4*)&ks[t * 132 + d4] =
            *(const float4*)(kc + (size_t)(seg * TCTX + t) * CDIM + h * HD + d4);
        *(float4*)&vs[t * 132 + d4] =
            *(const float4*)(vc + (size_t)(seg * TCTX + t) * CDIM + h * HD + d4);
    }
    __syncthreads();

    const float scale = 0.08838834764831845f;
    for (int tile = tid; tile < 16 * 33; tile += 256) {
        int st = tile / 33, tt = tile - st * 33;
        int s0 = st * 4, t0 = tt * 4;
        float a[4][4];
#pragma unroll
        for (int i = 0; i < 4; i++)
#pragma unroll
            for (int jj = 0; jj < 4; jj++) a[i][jj] = 0.f;
        for (int d = 0; d < 128; d += 4) {
            float4 qv[4], kv[4];
#pragma unroll
            for (int i = 0; i < 4; i++) qv[i] = *(const float4*)&qs[(s0 + i) * 128 + d];
#pragma unroll
            for (int jj = 0; jj < 4; jj++) kv[jj] = *(const float4*)&ks[(t0 + jj) * 132 + d];
#pragma unroll
            for (int i = 0; i < 4; i++)
#pragma unroll
                for (int jj = 0; jj < 4; jj++)
                    a[i][jj] += qv[i].x * kv[jj].x + qv[i].y * kv[jj].y
                              + qv[i].z * kv[jj].z + qv[i].w * kv[jj].w;
        }
#pragma unroll
        for (int i = 0; i < 4; i++)
#pragma unroll
            for (int jj = 0; jj < 4; jj++)
                ps[(s0 + i) * 132 + t0 + jj] = a[i][jj] * scale;
    }
    __syncthreads();

    int w = tid >> 5, l = tid & 31;
    for (int s = w; s < 64; s += 8) {
        float* pr = ps + s * 132;
        float mx = -1e30f;
        for (int t = l; t < 132; t += 32) mx = fmaxf(mx, pr[t]);
#pragma unroll
        for (int o = 16; o; o >>= 1) mx = fmaxf(mx, __shfl_xor_sync(0xffffffffu, mx, o));
        float sum = 0.f;
        for (int t = l; t < 132; t += 32) {
            float e = __expf(pr[t] - mx);
            pr[t] = e;
            sum += e;
        }
#pragma unroll
        for (int o = 16; o; o >>= 1) sum += __shfl_xor_sync(0xffffffffu, sum, o);
        float inv = 1.f / sum;
        for (int t = l; t < 132; t += 32) pr[t] *= inv;
    }
    __syncthreads();

    for (int tile = tid; tile < 16 * 32; tile += 256) {
        int st = tile >> 5, dt = tile & 31;
        int s0 = st * 4, d0 = dt * 4;
        float4 acc[4];
#pragma unroll
        for (int i = 0; i < 4; i++) acc[i] = make_float4(0.f, 0.f, 0.f, 0.f);
        for (int t = 0; t < 132; t += 4) {
            float4 pv[4], vv[4];
#pragma unroll
            for (int i = 0; i < 4; i++) pv[i] = *(const float4*)&ps[(s0 + i) * 132 + t];
#pragma unroll
            for (int jj = 0; jj < 4; jj++) vv[jj] = *(const float4*)&vs[(t + jj) * 132 + d0];
#pragma unroll
            for (int i = 0; i < 4; i++) {
                acc[i].x += pv[i].x * vv[0].x + pv[i].y * vv[1].x + pv[i].z * vv[2].x + pv[i].w * vv[3].x;
                acc[i].y += pv[i].x * vv[0].y + pv[i].y * vv[1].y + pv[i].z * vv[2].y + pv[i].w * vv[3].y;
                acc[i].z += pv[i].x * vv[0].z + pv[i].y * vv[1].z + pv[i].z * vv[2].z + pv[i].w * vv[3].z;
                acc[i].w += pv[i].x * vv[0].w + pv[i].y * vv[1].w + pv[i].z * vv[2].w + pv[i].w * vv[3].w;
            }
        }
#pragma unroll
        for (int i = 0; i < 4; i++) {
            size_t o = (size_t)(seg * SEGS + s0 + i) * CDIM + h * HD + d0;
            float y[4] = {acc[i].x, acc[i].y, acc[i].z, acc[i].w};
            union { __nv_bfloat162 b2[2]; uint2 u; } H, L;
#pragma unroll
            for (int jj = 0; jj < 2; jj++) {
                __nv_bfloat16 h0 = __float2bfloat16(y[2 * jj]);
                __nv_bfloat16 h1 = __float2bfloat16(y[2 * jj + 1]);
                H.b2[jj] = __nv_bfloat162(h0, h1);
                L.b2[jj] = __nv_bfloat162(
                    __float2bfloat16(y[2 * jj] - __bfloat162float(h0)),
                    __float2bfloat16(y[2 * jj + 1] - __bfloat162float(h1)));
            }
            *(uint2*)(oh + o) = H.u;
            *(uint2*)(ol + o) = L.u;
        }
    }
}

// ---- z = sigmoid(gate)*attno + x  -> bf16 h/l -----------------------------
__global__ void combine_k(const float* __restrict__ gl, const float* __restrict__ ao,
                          const float* __restrict__ x,
                          __nv_bfloat16* __restrict__ zh, __nv_bfloat16* __restrict__ zl,
                          int n4)
{
    int i = blockIdx.x * blockDim.x + threadIdx.x;
    if (i >= n4) return;
    float4 gv = ((const float4*)gl)[i];
    float4 av = ((const float4*)ao)[i];
    float4 xv = ((const float4*)x)[i];
    float y[4];
    y[0] = av.x / (1.f + __expf(-gv.x)) + xv.x;
    y[1] = av.y / (1.f + __expf(-gv.y)) + xv.y;
    y[2] = av.z / (1.f + __expf(-gv.z)) + xv.z;
    y[3] = av.w / (1.f + __expf(-gv.w)) + xv.w;
    union { __nv_bfloat162 b2[2]; uint2 u; } H, L;
#pragma unroll
    for (int jj = 0; jj < 2; jj++) {
        __nv_bfloat16 h0 = __float2bfloat16(y[2 * jj]);
        __nv_bfloat16 h1 = __float2bfloat16(y[2 * jj + 1]);
        H.b2[jj] = __nv_bfloat162(h0, h1);
        L.b2[jj] = __nv_bfloat162(
            __float2bfloat16(y[2 * jj] - __bfloat162float(h0)),
            __float2bfloat16(y[2 * jj + 1] - __bfloat162float(h1)));
    }
    ((uint2*)zh)[i] = H.u;
    ((uint2*)zl)[i] = L.u;
}

// ---------------------------------------------------------------------------
extern "C" void kernel_launch(void* const* d_in, const int* in_sizes, int n_in,
                              void* d_out, int out_size)
{
    (void)in_sizes; (void)n_in; (void)out_size;
    const float* x        = (const float*)d_in[0];
    const float* pm       = (const float*)d_in[1];
    const float* Wq       = (const float*)d_in[2];
    const float* Wk       = (const float*)d_in[3];
    const float* Wv       = (const float*)d_in[4];
    const float* mem_W1   = (const float*)d_in[5];
    const float* mem_b1   = (const float*)d_in[6];
    const float* ln1_g    = (const float*)d_in[7];
    const float* ln1_b    = (const float*)d_in[8];
    const float* mem_W2   = (const float*)d_in[9];
    const float* mem_b2   = (const float*)d_in[10];
    const float* ln2_g    = (const float*)d_in[11];
    const float* ln2_b    = (const float*)d_in[12];
    const float* mem_outW = (const float*)d_in[13];
    const float* mem_outb = (const float*)d_in[14];
    const float* mstate   = (const float*)d_in[15];
    const float* mha_Wq   = (const float*)d_in[16];
    const float* mha_bq   = (const float*)d_in[17];
    const float* mha_Wk   = (const float*)d_in[18];
    const float* mha_bk   = (const float*)d_in[19];
    const float* mha_Wv   = (const float*)d_in[20];
    const float* mha_bv   = (const float*)d_in[21];
    const float* mha_Wo   = (const float*)d_in[22];
    const float* mha_bo   = (const float*)d_in[23];
    const float* gn_g     = (const float*)d_in[24];
    const float* gn_b     = (const float*)d_in[25];
    const float* gate_W   = (const float*)d_in[26];
    const float* gate_b   = (const float*)d_in[27];
    const float* out_W    = (const float*)d_in[28];
    const float* out_b    = (const float*)d_in[29];
    float* out = (float*)d_out;

    float *K2, *V2, *kpm, *vpm, *bkret, *bvret;
    float *mA, *qb, *kctx, *vctx, *attno, *gate;
    __nv_bfloat16 *xh, *xl, *sh, *sl, *mbh, *mbl;
    __nv_bfloat16 *q2h, *q2l, *k2h, *k2l, *v2h, *v2l, *amh, *aml;
    __nv_bfloat16 *kmh, *kml, *vmh, *vml, *woh, *wol, *gwh, *gwl, *owh, *owl;
    __nv_bfloat16 *mwqh, *mwql, *mwkh, *mwkl, *mwvh, *mwvl;
    __nv_bfloat16 *wqth, *wqtl, *wkth, *wktl, *wvth, *wvtl;
    __nv_bfloat16 *mw1h, *mw1l, *mowth, *mowtl, *w2h, *w2l;
    cudaGetSymbolAddress((void**)&K2, g_K2);
    cudaGetSymbolAddress((void**)&V2, g_V2);
    cudaGetSymbolAddress((void**)&kpm, g_kpm);
    cudaGetSymbolAddress((void**)&vpm, g_vpm);
    cudaGetSymbolAddress((void**)&bkret, g_bkret);
    cudaGetSymbolAddress((void**)&bvret, g_bvret);
    cudaGetSymbolAddress((void**)&mA, g_mA);
    cudaGetSymbolAddress((void**)&qb, g_qb);
    cudaGetSymbolAddress((void**)&kctx, g_kctx);
    cudaGetSymbolAddress((void**)&vctx, g_vctx);
    cudaGetSymbolAddress((void**)&attno, g_attno);
    cudaGetSymbolAddress((void**)&gate, g_gate);
    cudaGetSymbolAddress((void**)&xh, g_xh);   cudaGetSymbolAddress((void**)&xl, g_xl);
    cudaGetSymbolAddress((void**)&sh, g_sh);   cudaGetSymbolAddress((void**)&sl, g_sl);
    cudaGetSymbolAddress((void**)&mbh, g_mbh); cudaGetSymbolAddress((void**)&mbl, g_mbl);
    cudaGetSymbolAddress((void**)&q2h, g_q2h); cudaGetSymbolAddress((void**)&q2l, g_q2l);
    cudaGetSymbolAddress((void**)&k2h, g_k2h); cudaGetSymbolAddress((void**)&k2l, g_k2l);
    cudaGetSymbolAddress((void**)&v2h, g_v2h); cudaGetSymbolAddress((void**)&v2l, g_v2l);
    cudaGetSymbolAddress((void**)&amh, g_amh); cudaGetSymbolAddress((void**)&aml, g_aml);
    cudaGetSymbolAddress((void**)&kmh, g_kmh); cudaGetSymbolAddress((void**)&kml, g_kml);
    cudaGetSymbolAddress((void**)&vmh, g_vmh); cudaGetSymbolAddress((void**)&vml, g_vml);
    cudaGetSymbolAddress((void**)&woh, g_woh); cudaGetSymbolAddress((void**)&wol, g_wol);
    cudaGetSymbolAddress((void**)&gwh, g_gwh); cudaGetSymbolAddress((void**)&gwl, g_gwl);
    cudaGetSymbolAddress((void**)&owh, g_owh); cudaGetSymbolAddress((void**)&owl, g_owl);
    cudaGetSymbolAddress((void**)&mwqh, g_mwqh); cudaGetSymbolAddress((void**)&mwql, g_mwql);
    cudaGetSymbolAddress((void**)&mwkh, g_mwkh); cudaGetSymbolAddress((void**)&mwkl, g_mwkl);
    cudaGetSymbolAddress((void**)&mwvh, g_mwvh); cudaGetSymbolAddress((void**)&mwvl, g_mwvl);
    cudaGetSymbolAddress((void**)&wqth, g_wqth); cudaGetSymbolAddress((void**)&wqtl, g_wqtl);
    cudaGetSymbolAddress((void**)&wkth, g_wkth); cudaGetSymbolAddress((void**)&wktl, g_wktl);
    cudaGetSymbolAddress((void**)&wvth, g_wvth); cudaGetSymbolAddress((void**)&wvtl, g_wvtl);
    cudaGetSymbolAddress((void**)&mw1h, g_mw1h); cudaGetSymbolAddress((void**)&mw1l, g_mw1l);
    cudaGetSymbolAddress((void**)&mowth, g_mowth); cudaGetSymbolAddress((void**)&mowtl, g_mowtl);
    cudaGetSymbolAddress((void**)&w2h, g_w2h); cudaGetSymbolAddress((void**)&w2l, g_w2l);

    static bool attr_done = false;
    if (!attr_done) {
        cudaFuncSetAttribute(attn_k, cudaFuncAttributeMaxDynamicSharedMemorySize, ATTN_SMEM);
        cudaFuncSetAttribute(tmma_k, cudaFuncAttributeMaxDynamicSharedMemorySize, TM_SMEM);
        attr_done = true;
    }

    const int BIG = 1 << 30;

    TgBatch tb;
    auto tb_reset = [&]() { tb.njobs = 0; tb.prefix[0] = 0; };
    auto tb_add = [&](const __nv_bfloat16* ah, const __nv_bfloat16* al,
                      const __nv_bfloat16* bh, const __nv_bfloat16* bl,
                      const float* bias, float* C, __nv_bfloat16* Ch, __nv_bfloat16* Cl,
                      int M, int N, int K, int sr, int ss, int ro) {
        int j = tb.njobs++;
        tb.tilesN[j] = N / 128;
        tb.prefix[j + 1] = tb.prefix[j] + (M / 128) * (N / 128);
        tb.Ah[j] = ah; tb.Al[j] = al; tb.Bh[j] = bh; tb.Bl[j] = bl;
        tb.bias[j] = bias; tb.C[j] = C; tb.Ch[j] = Ch; tb.Cl[j] = Cl;
        tb.K[j] = K; tb.N[j] = N; tb.sr[j] = sr; tb.ss[j] = ss; tb.ro[j] = ro;
    };
    auto tb_go = [&]() {
        tmma_k<<<tb.prefix[tb.njobs], 256, TM_SMEM>>>(tb);
    };

    // ---- L0: all plain splits in ONE launch ----
    SpBatch sp; sp.njobs = 0; sp.prefix[0] = 0;
    auto sp_add = [&](const float* in, __nv_bfloat16* h, __nv_bfloat16* l, int n) {
        int j = sp.njobs++;
        sp.prefix[j + 1] = sp.prefix[j] + n / 8;
        sp.in[j] = in; sp.h[j] = h; sp.l[j] = l;
    };
    sp_add(x, xh, xl, NROWS * CDIM);
    sp_add(mha_Wq, mwqh, mwql, CDIM * CDIM);
    sp_add(mha_Wk, mwkh, mwkl, CDIM * CDIM);
    sp_add(mha_Wv, mwvh, mwvl, CDIM * CDIM);
    sp_add(mem_W1, mw1h, mw1l, MDIM * CDIM);
    sp_add(mem_W2, w2h, w2l, MDIM * MDIM);
    sp_add(mha_Wo, woh, wol, CDIM * CDIM);
    sp_add(gate_W, gwh, gwl, CDIM * CDIM);
    sp_add(out_W, owh, owl, CDIM * CDIM);
    split_k<<<(sp.prefix[sp.njobs] + 255) / 256, 256>>>(sp);

    // ---- L1: all transpose+splits in ONE launch ----
    TsBatch ts;
    ts.in[0] = Wq; ts.h[0] = wqth; ts.l[0] = wqtl; ts.R[0] = 1024; ts.Cc[0] = 1024;
    ts.in[1] = Wk; ts.h[1] = wkth; ts.l[1] = wktl; ts.R[1] = 1024; ts.Cc[1] = 1024;
    ts.in[2] = Wv; ts.h[2] = wvth; ts.l[2] = wvtl; ts.R[2] = 1024; ts.Cc[2] = 1024;
    ts.in[3] = mem_outW; ts.h[3] = mowth; ts.l[3] = mowtl; ts.R[3] = 1024; ts.Cc[3] = 128;
    tsplit_k<<<dim3(32, 32, 4), dim3(32, 8)>>>(ts);

    // ---- L2: batch {Q2, K2, V2, Amat} ----
    tb_reset();
    tb_add(mwqh, mwql, wqth, wqtl, nullptr, nullptr, q2h, q2l, 1024, 1024, 1024, BIG, 0, 0);
    tb_add(mwkh, mwkl, wkth, wktl, nullptr, K2, k2h, k2l, 1024, 1024, 1024, BIG, 0, 0);
    tb_add(mwvh, mwvl, wvth, wvtl, nullptr, V2, v2h, v2l, 1024, 1024, 1024, BIG, 0, 0);
    tb_add(mw1h, mw1l, wqth, wqtl, nullptr, nullptr, amh, aml, 128, 1024, 1024, BIG, 0, 0);
    tb_go();

    // ---- L3+L5 merged: {KM, VM, memnet1, q-proj, k-proj, v-proj} ----
    // All depend only on L2 outputs + xh; small tiles fill the big launch's tail.
    tb_reset();
    tb_add(xh, xl, q2h, q2l, mha_bq, qb, nullptr, nullptr, NROWS, 1024, 1024, BIG, 0, 0);
    tb_add(xh, xl, k2h, k2l, mha_bk, kctx, nullptr, nullptr, NROWS, 1024, 1024, SEGS, TCTX, SEGS + PDIM);
    tb_add(xh, xl, v2h, v2l, mha_bv, vctx, nullptr, nullptr, NROWS, 1024, 1024, SEGS, TCTX, SEGS + PDIM);
    tb_add(k2h, k2l, mowth, mowtl, nullptr, nullptr, kmh, kml, 1024, 128, 1024, BIG, 0, 0);
    tb_add(v2h, v2l, mowth, mowtl, nullptr, nullptr, vmh, vml, 1024, 128, 1024, BIG, 0, 0);
    tb_add(xh, xl, amh, aml, mem_b1, mA, nullptr, nullptr, NROWS, 128, 1024, BIG, 0, 0);
    tb_go();

    // ---- memnorm1 ----
    memnorm_k<<<NROWS, 128>>>(mA, ln1_g, ln1_b, nullptr, sh, sl, 1);

    // ---- memory net part 2 ----
    tb_reset();
    tb_add(sh, sl, w2h, w2l, mem_b2, mA, nullptr, nullptr, NROWS, 128, 128, BIG, 0, 0);
    tb_go();
    memnorm_k<<<NROWS, 128>>>(mA, ln2_g, ln2_b, mstate, mbh, mbl, 0);

    pmproj_k<<<32, 256>>>(pm, K2, V2, mha_bk, mha_bv, kpm, vpm);
    bias_ret_k<<<8, 256>>>(K2, V2, mem_outb, mha_bk, mha_bv, bkret, bvret);

    // ---- batch {k-ret, v-ret} ----
    tb_reset();
    tb_add(mbh, mbl, kmh, kml, bkret, kctx, nullptr, nullptr, NROWS, 1024, 128, SEGS, TCTX, 0);
    tb_add(mbh, mbl, vmh, vml, bvret, vctx, nullptr, nullptr, NROWS, 1024, 128, SEGS, TCTX, 0);
    tb_go();

    copy_pm_k<<<(NSEG * PDIM * CDIM + 255) / 256, 256>>>(kpm, vpm, kctx, vctx);

    // ---- attention -> bf16 h/l directly ----
    attn_k<<<dim3(HEADS, NSEG), 256, ATTN_SMEM>>>(qb, kctx, vctx, sh, sl);

    // ---- output projection, gate, final ----
    tb_reset();
    tb_add(sh, sl, woh, wol, mha_bo, attno, nullptr, nullptr, NROWS, 1024, 1024, BIG, 0, 0);
    tb_go();
    ln1024_k<<<NROWS, 256>>>(attno, gn_g, gn_b, sh, sl);
    tb_reset();
    tb_add(sh, sl, gwh, gwl, gate_b, gate, nullptr, nullptr, NROWS, 1024, 1024, BIG, 0, 0);
    tb_go();
    combine_k<<<(NROWS * CDIM / 4 + 255) / 256, 256>>>(gate, attno, x, sh, sl, NROWS * CDIM / 4);
    tb_reset();
    tb_add(sh, sl, owh, owl, out_b, out, nullptr, nullptr, NROWS, 1024, 1024, BIG, 0, 0);
    tb_go();
}

// round 11
// speedup vs baseline: 1.1422x; 1.0042x over previous
#include <cuda_runtime.h>
#include <cuda_bf16.h>
#include <cstdint>

// Problem constants
#define NROWS 16384      // B*L
#define CDIM  1024
#define MDIM  128
#define NSEG  256
#define SEGS  64
#define TCTX  132
#define PDIM  4
#define HEADS 8
#define HD    128

// ===================== helpers (base sm_103 PTX only) ======================
__device__ __forceinline__ uint32_t smem_u32(const void* p) {
    uint32_t a;
    asm("{ .reg .u64 t; cvta.to.shared.u64 t, %1; cvt.u32.u64 %0, t; }" : "=r"(a) : "l"(p));
    return a;
}
__device__ __forceinline__ void ldsm4(uint32_t* r, uint32_t a) {
    asm volatile("ldmatrix.sync.aligned.m8n8.x4.shared.b16 {%0,%1,%2,%3}, [%4];"
        : "=r"(r[0]), "=r"(r[1]), "=r"(r[2]), "=r"(r[3]) : "r"(a));
}
__device__ __forceinline__ void mma16816(float* c, const uint32_t* a, const uint32_t* b) {
    asm volatile(
        "mma.sync.aligned.m16n8k16.row.col.f32.bf16.bf16.f32 "
        "{%0,%1,%2,%3}, {%4,%5,%6,%7}, {%8,%9}, {%0,%1,%2,%3};"
        : "+f"(c[0]), "+f"(c[1]), "+f"(c[2]), "+f"(c[3])
        : "r"(a[0]), "r"(a[1]), "r"(a[2]), "r"(a[3]), "r"(b[0]), "r"(b[1]));
}
__device__ __forceinline__ void cpasync16(uint32_t dst, const void* src) {
    asm volatile("cp.async.cg.shared.global [%0], [%1], 16;" :: "r"(dst), "l"(src));
}
#define CP_COMMIT() asm volatile("cp.async.commit_group;" ::: "memory")
#define CP_WAIT2()  asm volatile("cp.async.wait_group 2;" ::: "memory")
#define CP_WAIT1()  asm volatile("cp.async.wait_group 1;" ::: "memory")
#define CP_WAIT0()  asm volatile("cp.async.wait_group 0;" ::: "memory")

// ---------------- scratch (device globals) ---------------------------------
__device__ float g_K2[CDIM*CDIM];
__device__ float g_V2[CDIM*CDIM];
__device__ float g_kpm[PDIM*CDIM];
__device__ float g_vpm[PDIM*CDIM];
__device__ float g_bkret[CDIM];
__device__ float g_bvret[CDIM];
__device__ float g_mA[NROWS*MDIM];
__device__ float g_qb[NROWS*CDIM];
__device__ float g_kctx[NSEG*TCTX*CDIM];
__device__ float g_vctx[NSEG*TCTX*CDIM];
__device__ float g_attno[NROWS*CDIM];
__device__ float g_gate[NROWS*CDIM];
// bf16 hi/lo
__device__ __nv_bfloat16 g_xh[NROWS*CDIM],  g_xl[NROWS*CDIM];
__device__ __nv_bfloat16 g_sh[NROWS*CDIM],  g_sl[NROWS*CDIM];
__device__ __nv_bfloat16 g_mbh[NROWS*MDIM], g_mbl[NROWS*MDIM];
__device__ __nv_bfloat16 g_q2h[CDIM*CDIM],  g_q2l[CDIM*CDIM];
__device__ __nv_bfloat16 g_k2h[CDIM*CDIM],  g_k2l[CDIM*CDIM];
__device__ __nv_bfloat16 g_v2h[CDIM*CDIM],  g_v2l[CDIM*CDIM];
__device__ __nv_bfloat16 g_amh[MDIM*CDIM],  g_aml[MDIM*CDIM];
__device__ __nv_bfloat16 g_kmh[CDIM*MDIM],  g_kml[CDIM*MDIM];
__device__ __nv_bfloat16 g_vmh[CDIM*MDIM],  g_vml[CDIM*MDIM];
__device__ __nv_bfloat16 g_woh[CDIM*CDIM],  g_wol[CDIM*CDIM];
__device__ __nv_bfloat16 g_gwh[CDIM*CDIM],  g_gwl[CDIM*CDIM];
__device__ __nv_bfloat16 g_owh[CDIM*CDIM],  g_owl[CDIM*CDIM];
__device__ __nv_bfloat16 g_mwqh[CDIM*CDIM], g_mwql[CDIM*CDIM];
__device__ __nv_bfloat16 g_mwkh[CDIM*CDIM], g_mwkl[CDIM*CDIM];
__device__ __nv_bfloat16 g_mwvh[CDIM*CDIM], g_mwvl[CDIM*CDIM];
__device__ __nv_bfloat16 g_wqth[CDIM*CDIM], g_wqtl[CDIM*CDIM];
__device__ __nv_bfloat16 g_wkth[CDIM*CDIM], g_wktl[CDIM*CDIM];
__device__ __nv_bfloat16 g_wvth[CDIM*CDIM], g_wvtl[CDIM*CDIM];
__device__ __nv_bfloat16 g_mw1h[MDIM*CDIM], g_mw1l[MDIM*CDIM];
__device__ __nv_bfloat16 g_mowth[MDIM*CDIM], g_mowtl[MDIM*CDIM];
__device__ __nv_bfloat16 g_w2h[MDIM*MDIM],  g_w2l[MDIM*MDIM];

__device__ __forceinline__ uint32_t sw64(uint32_t b) { return b ^ ((b >> 3) & 0x30); }

// ============ batched HMMA bf16x3 GEMM, cp.async 3-stage pipeline ==========
#define BK 32
#define TILE_B (128*BK*2)          // 8192 bytes per tile
#define STG_B  (4*TILE_B)          // 32768 per stage
#define NSTG   3
#define TM_SMEM (NSTG*STG_B)       // 98304
#define MAXJ 8

struct TgBatch {
    int njobs;
    int prefix[MAXJ + 1];
    int tilesN[MAXJ];
    const __nv_bfloat16 *Ah[MAXJ], *Al[MAXJ], *Bh[MAXJ], *Bl[MAXJ];
    const float* bias[MAXJ];
    float* C[MAXJ];
    __nv_bfloat16 *Ch[MAXJ], *Cl[MAXJ];
    int K[MAXJ], N[MAXJ], sr[MAXJ], ss[MAXJ], ro[MAXJ];
};

__global__ __launch_bounds__(256, 2) void tmma_k(TgBatch bat)
{
    extern __shared__ char sm[];
    uint32_t sb = smem_u32(sm);
    int tid = threadIdx.x, wid = tid >> 5, lane = tid & 31;

    int bt = blockIdx.x;
    int j = 0;
#pragma unroll
    for (int t = 1; t < MAXJ; t++)
        if (t < bat.njobs && bt >= bat.prefix[t]) j = t;
    int local = bt - bat.prefix[j];
    int tN = bat.tilesN[j];
    int tileN = local % tN;
    int tileM = local / tN;

    const __nv_bfloat16* jAh = bat.Ah[j];
    const __nv_bfloat16* jAl = bat.Al[j];
    const __nv_bfloat16* jBh = bat.Bh[j];
    const __nv_bfloat16* jBl = bat.Bl[j];
    const float* jbias = bat.bias[j];
    float* jC = bat.C[j];
    __nv_bfloat16* jCh = bat.Ch[j];
    __nv_bfloat16* jCl = bat.Cl[j];
    int K = bat.K[j], N = bat.N[j];
    int seg_rows = bat.sr[j], seg_stride = bat.ss[j], row_off = bat.ro[j];

    int wm = wid & 1, wn = wid >> 1;

    int row_ld = tid >> 2, c16 = tid & 3;
    int row_ld1 = (tid + 256) >> 2, c161 = (tid + 256) & 3;
    uint32_t dst_sw0 = sw64((uint32_t)(row_ld * 64 + c16 * 16));
    uint32_t dst_sw1 = sw64((uint32_t)(row_ld1 * 64 + c161 * 16));

    const __nv_bfloat16* p0[4];
    ptrdiff_t pdel = (ptrdiff_t)(row_ld1 - row_ld) * K + (ptrdiff_t)(c161 - c16) * 8;
    {
        const __nv_bfloat16* base[4] = {
            jAh + (size_t)tileM * 128 * K, jAl + (size_t)tileM * 128 * K,
            jBh + (size_t)tileN * 128 * K, jBl + (size_t)tileN * 128 * K };
#pragma unroll
        for (int t = 0; t < 4; t++)
            p0[t] = base[t] + (size_t)row_ld * K + c16 * 8;
    }
    auto LOADS = [&](int stage) {
        uint32_t sbase = sb + stage * STG_B;
#pragma unroll
        for (int t = 0; t < 4; t++) {
            cpasync16(sbase + t * TILE_B + dst_sw0, p0[t]);
            cpasync16(sbase + t * TILE_B + dst_sw1, p0[t] + pdel);
            p0[t] += BK;
        }
    };

    int mi = lane >> 3, li = lane & 7;
    uint32_t arow[4], brow[2];
#pragma unroll
    for (int mt = 0; mt < 4; mt++)
        arow[mt] = (uint32_t)((wm * 64 + mt * 16 + (mi & 1) * 8 + li) * 64);
#pragma unroll
    for (int p = 0; p < 2; p++)
        brow[p] = (uint32_t)((wn * 32 + p * 16 + (mi & 1) * 8 + li) * 64);
    uint32_t kfr = (uint32_t)((mi >> 1) * 16);

    float acc[4][4][4];
#pragma unroll
    for (int a = 0; a < 4; a++)
#pragma unroll
        for (int b = 0; b < 4; b++)
#pragma unroll
            for (int r = 0; r < 4; r++) acc[a][b][r] = 0.f;

    int nchunk = K / BK;
    LOADS(0); CP_COMMIT();
    LOADS(1); CP_COMMIT();

    int cs = 0, ls = 2;
    for (int c = 0; c < nchunk; c++) {
        if (c + 2 < nchunk) {
            LOADS(ls); CP_COMMIT();
            if (++ls == NSTG) ls = 0;
            CP_WAIT2();
        } else if (c + 1 < nchunk) CP_WAIT1();
        else CP_WAIT0();
        __syncthreads();

        uint32_t sbase = sb + cs * STG_B;
        uint32_t bfh[4][2], bfl[4][2], af[2][2][4];   // A double-buffered
#pragma unroll
        for (int ks = 0; ks < 2; ks++) {
            uint32_t kb = kfr + ks * 32;
#pragma unroll
            for (int p = 0; p < 2; p++) {
                uint32_t r[4];
                ldsm4(r, sbase + 2 * TILE_B + sw64(brow[p] + kb));
                bfh[2 * p][0] = r[0]; bfh[2 * p][1] = r[2];
                bfh[2 * p + 1][0] = r[1]; bfh[2 * p + 1][1] = r[3];
                ldsm4(r, sbase + 3 * TILE_B + sw64(brow[p] + kb));
                bfl[2 * p][0] = r[0]; bfl[2 * p][1] = r[2];
                bfl[2 * p + 1][0] = r[1]; bfl[2 * p + 1][1] = r[3];
            }
            // preload mt=0 fragments
            ldsm4(af[0][0], sbase + 0 * TILE_B + sw64(arow[0] + kb));
            ldsm4(af[0][1], sbase + 1 * TILE_B + sw64(arow[0] + kb));
#pragma unroll
            for (int mt = 0; mt < 4; mt++) {
                int cur = mt & 1, nxt = cur ^ 1;
                if (mt < 3) {   // prefetch mt+1 before current MMAs
                    ldsm4(af[nxt][0], sbase + 0 * TILE_B + sw64(arow[mt + 1] + kb));
                    ldsm4(af[nxt][1], sbase + 1 * TILE_B + sw64(arow[mt + 1] + kb));
                }
#pragma unroll
                for (int nt = 0; nt < 4; nt++) mma16816(acc[mt][nt], af[cur][0], bfh[nt]);
#pragma unroll
                for (int nt = 0; nt < 4; nt++) mma16816(acc[mt][nt], af[cur][0], bfl[nt]);
#pragma unroll
                for (int nt = 0; nt < 4; nt++) mma16816(acc[mt][nt], af[cur][1], bfh[nt]);
            }
        }
        if (++cs == NSTG) cs = 0;
        __syncthreads();
    }

    // epilogue
    int g = lane >> 2, t4 = lane & 3;
#pragma unroll
    for (int mt = 0; mt < 4; mt++) {
#pragma unroll
        for (int half = 0; half < 2; half++) {
            int rowg = tileM * 128 + wm * 64 + mt * 16 + half * 8 + g;
            int orow = (rowg / seg_rows) * seg_stride + row_off + (rowg % seg_rows);
            size_t rbase = (size_t)orow * N + tileN * 128 + wn * 32;
            const float* brows = jbias ? (jbias + tileN * 128 + wn * 32) : nullptr;
#pragma unroll
            for (int nt = 0; nt < 4; nt++) {
                int col = nt * 8 + t4 * 2;
                float vx = acc[mt][nt][half * 2 + 0];
                float vy = acc[mt][nt][half * 2 + 1];
                if (brows) { vx += brows[col]; vy += brows[col + 1]; }
                if (jC) *(float2*)(jC + rbase + col) = make_float2(vx, vy);
                if (jCh) {
                    __nv_bfloat16 hx = __float2bfloat16(vx);
                    __nv_bfloat16 hy = __float2bfloat16(vy);
                    *(__nv_bfloat162*)(jCh + rbase + col) = __nv_bfloat162(hx, hy);
                    *(__nv_bfloat162*)(jCl + rbase + col) = __nv_bfloat162(
                        __float2bfloat16(vx - __bfloat162float(hx)),
                        __float2bfloat16(vy - __bfloat162float(hy)));
                }
            }
        }
    }
}

// ---- batched fp32 -> bf16 hi/lo split -------------------------------------
#define MAXS 9
struct SpBatch {
    int njobs;
    int prefix[MAXS + 1];
    const float* in[MAXS];
    __nv_bfloat16 *h[MAXS], *l[MAXS];
};
__global__ void split_k(SpBatch bat)
{
    int gi = blockIdx.x * blockDim.x + threadIdx.x;
    if (gi >= bat.prefix[bat.njobs]) return;
    int j = 0;
#pragma unroll
    for (int t = 1; t < MAXS; t++)
        if (t < bat.njobs && gi >= bat.prefix[t]) j = t;
    int i = gi - bat.prefix[j];
    const float* in = bat.in[j];
    float4 a = ((const float4*)in)[2 * i];
    float4 b = ((const float4*)in)[2 * i + 1];
    float v[8] = {a.x, a.y, a.z, a.w, b.x, b.y, b.z, b.w};
    union { __nv_bfloat162 h2[4]; uint4 u; } H, L;
#pragma unroll
    for (int t = 0; t < 4; t++) {
        __nv_bfloat16 h0 = __float2bfloat16(v[2 * t]);
        __nv_bfloat16 h1 = __float2bfloat16(v[2 * t + 1]);
        H.h2[t] = __nv_bfloat162(h0, h1);
        L.h2[t] = __nv_bfloat162(
            __float2bfloat16(v[2 * t] - __bfloat162float(h0)),
            __float2bfloat16(v[2 * t + 1] - __bfloat162float(h1)));
    }
    ((uint4*)bat.h[j])[i] = H.u;
    ((uint4*)bat.l[j])[i] = L.u;
}

// ---- batched fused transpose + split --------------------------------------
struct TsBatch {
    const float* in[4];
    __nv_bfloat16 *h[4], *l[4];
    int R[4], Cc[4];
};
__global__ void tsplit_k(TsBatch bat)
{
    int z = blockIdx.z;
    int R = bat.R[z], Cc = bat.Cc[z];
    int bx = blockIdx.x * 32, by = blockIdx.y * 32;
    if (bx >= Cc || by >= R) return;
    __shared__ float tile[32][33];
    int tx = threadIdx.x, ty = threadIdx.y;
    const float* in = bat.in[z];
#pragma unroll
    for (int jj = 0; jj < 4; jj++)
        tile[ty + 8 * jj][tx] = in[(size_t)(by + ty + 8 * jj) * Cc + bx + tx];
    __syncthreads();
#pragma unroll
    for (int jj = 0; jj < 4; jj++) {
        float v = tile[tx][ty + 8 * jj];
        __nv_bfloat16 hv = __float2bfloat16(v);
        size_t o = (size_t)(bx + ty + 8 * jj) * R + by + tx;
        bat.h[z][o] = hv;
        bat.l[z][o] = __float2bfloat16(v - __bfloat162float(hv));
    }
}

// ---- memory-net row norm -> bf16 h/l --------------------------------------
__global__ __launch_bounds__(128) void memnorm_k(
    const float* __restrict__ in, const float* __restrict__ g,
    const float* __restrict__ b, const float* __restrict__ add,
    __nv_bfloat16* __restrict__ oh, __nv_bfloat16* __restrict__ ol, int do_silu)
{
    int r = blockIdx.x, t = threadIdx.x;
    float v = in[(size_t)r * 128 + t];
    if (do_silu) v = v / (1.f + __expf(-v));
    __shared__ float ws[4];
    int w = t >> 5, l = t & 31;
    float s = v;
#pragma unroll
    for (int o = 16; o; o >>= 1) s += __shfl_xor_sync(0xffffffffu, s, o);
    if (l == 0) ws[w] = s;
    __syncthreads();
    float mu = (ws[0] + ws[1] + ws[2] + ws[3]) * (1.f / 128.f);
    __syncthreads();
    float d = v - mu;
    float s2 = d * d;
#pragma unroll
    for (int o = 16; o; o >>= 1) s2 += __shfl_xor_sync(0xffffffffu, s2, o);
    if (l == 0) ws[w] = s2;
    __syncthreads();
    float var = (ws[0] + ws[1] + ws[2] + ws[3]) * (1.f / 128.f);
    float y = d * rsqrtf(var + 1e-5f) * g[t] + b[t];
    if (add) y += add[t];
    __nv_bfloat16 hv = __float2bfloat16(y);
    oh[(size_t)r * 128 + t] = hv;
    ol[(size_t)r * 128 + t] = __float2bfloat16(y - __bfloat162float(hv));
}

// ---- LayerNorm(1024) -> bf16 h/l ------------------------------------------
__global__ __launch_bounds__(256) void ln1024_k(
    const float* __restrict__ in, const float* __restrict__ g,
    const float* __restrict__ b, __nv_bfloat16* __restrict__ oh,
    __nv_bfloat16* __restrict__ ol)
{
    int r = blockIdx.x, t = threadIdx.x;
    const float* row = in + (size_t)r * 1024;
    float4 v = *(const float4*)(row + t * 4);
    __shared__ float ws[8];
    int w = t >> 5, l = t & 31;
    float s = v.x + v.y + v.z + v.w;
#pragma unroll
    for (int o = 16; o; o >>= 1) s += __shfl_xor_sync(0xffffffffu, s, o);
    if (l == 0) ws[w] = s;
    __syncthreads();
    float mu = 0.f;
#pragma unroll
    for (int i = 0; i < 8; i++) mu += ws[i];
    mu *= (1.f / 1024.f);
    __syncthreads();
    float dx = v.x - mu, dy = v.y - mu, dz = v.z - mu, dw = v.w - mu;
    float s2 = dx * dx + dy * dy + dz * dz + dw * dw;
#pragma unroll
    for (int o = 16; o; o >>= 1) s2 += __shfl_xor_sync(0xffffffffu, s2, o);
    if (l == 0) ws[w] = s2;
    __syncthreads();
    float var = 0.f;
#pragma unroll
    for (int i = 0; i < 8; i++) var += ws[i];
    var *= (1.f / 1024.f);
    float inv = rsqrtf(var + 1e-5f);
    float4 gg = *(const float4*)(g + t * 4);
    float4 bb = *(const float4*)(b + t * 4);
    float y[4] = { dx * inv * gg.x + bb.x, dy * inv * gg.y + bb.y,
                   dz * inv * gg.z + bb.z, dw * inv * gg.w + bb.w };
    union { __nv_bfloat162 b2[2]; uint2 u; } H, L;
#pragma unroll
    for (int jj = 0; jj < 2; jj++) {
        __nv_bfloat16 h0 = __float2bfloat16(y[2 * jj]);
        __nv_bfloat16 h1 = __float2bfloat16(y[2 * jj + 1]);
        H.b2[jj] = __nv_bfloat162(h0, h1);
        L.b2[jj] = __nv_bfloat162(
            __float2bfloat16(y[2 * jj] - __bfloat162float(h0)),
            __float2bfloat16(y[2 * jj + 1] - __bfloat162float(h1)));
    }
    *(uint2*)(oh + (size_t)r * 1024 + t * 4) = H.u;
    *(uint2*)(ol + (size_t)r * 1024 + t * 4) = L.u;
}

// ---- persistent-memory k/v rows -------------------------------------------
__global__ void pmproj_k(const float* __restrict__ pm,
                         const float* __restrict__ K2, const float* __restrict__ V2,
                         const float* __restrict__ bk, const float* __restrict__ bv,
                         float* __restrict__ kpm, float* __restrict__ vpm)
{
    int i = blockIdx.x * blockDim.x + threadIdx.x;
    if (i >= 2 * PDIM * CDIM) return;
    int which = i >> 12;
    int p = (i >> 10) & 3;
    int n = i & 1023;
    const float* W = (which ? V2 : K2) + (size_t)n * 1024;
    const float* row = pm + p * 1024;
    float acc = which ? bv[n] : bk[n];
#pragma unroll 4
    for (int c = 0; c < 1024; c += 4) {
        float4 a = *(const float4*)(row + c);
        float4 w = *(const float4*)(W + c);
        acc += a.x * w.x + a.y * w.y + a.z * w.z + a.w * w.w;
    }
    (which ? vpm : kpm)[p * 1024 + n] = acc;
}

// ---- biases for retrieved k/v rows ----------------------------------------
__global__ void bias_ret_k(const float* __restrict__ K2, const float* __restrict__ V2,
                           const float* __restrict__ mob,
                           const float* __restrict__ bk, const float* __restrict__ bv,
                           float* __restrict__ ok, float* __restrict__ ov)
{
    int n = blockIdx.x * blockDim.x + threadIdx.x;
    if (n < 1024) {
        float a = bk[n];
        for (int c = 0; c < 1024; c++) a += K2[n * 1024 + c] * mob[c];
        ok[n] = a;
    } else if (n < 2048) {
        int m = n - 1024;
        float a = bv[m];
        for (int c = 0; c < 1024; c++) a += V2[m * 1024 + c] * mob[c];
        ov[m] = a;
    }
}

// ---- broadcast pm k/v into every segment ----------------------------------
__global__ void copy_pm_k(const float* __restrict__ kpm, const float* __restrict__ vpm,
                          float* __restrict__ kctx, float* __restrict__ vctx)
{
    int i = blockIdx.x * blockDim.x + threadIdx.x;
    if (i >= NSEG * PDIM * CDIM) return;
    int seg = i >> 12;
    int rem = i & 4095;
    size_t dst = ((size_t)seg * TCTX + SEGS) * CDIM + rem;
    kctx[dst] = kpm[rem];
    vctx[dst] = vpm[rem];
}

// ---- attention: register-tiled 4x4, all LDS.128 ---------------------------
#define ATTN_SMEM ((64*128 + 2*132*132 + 64*132) * 4)
__global__ __launch_bounds__(256) void attn_k(
    const float* __restrict__ q, const float* __restrict__ kc,
    const float* __restrict__ vc,
    __nv_bfloat16* __restrict__ oh, __nv_bfloat16* __restrict__ ol)
{
    extern __shared__ float smf[];
    float* qs = smf;
    float* ks = qs + 64 * 128;
    float* vs = ks + 132 * 132;
    float* ps = vs + 132 * 132;
    int h = blockIdx.x, seg = blockIdx.y;
    int tid = threadIdx.x;

    for (int i = tid; i < 64 * 32; i += 256) {
        int s = i >> 5, d4 = (i & 31) << 2;
        *(float4*)&qs[s * 128 + d4] =
            *(const float4*)(q + (size_t)(seg * SEGS + s) * CDIM + h * HD + d4);
    }
    for (int i = tid; i < 132 * 32; i += 256) {
        int t = i >> 5, d4 = (i & 31) << 2;
        *(float4*)&ks[t * 132 + d4] =
            *(const float4*)(kc + (size_t)(seg * TCTX + t) * CDIM + h * HD + d4);
        *(float4*)&vs[t * 132 + d4] =
            *(const float4*)(vc + (size_t)(seg * TCTX + t) * CDIM + h * HD + d4);
    }
    __syncthreads();

    const float scale = 0.08838834764831845f;
    for (int tile = tid; tile < 16 * 33; tile += 256) {
        int st = tile / 33, tt = tile - st * 33;
        int s0 = st * 4, t0 = tt * 4;
        float a[4][4];
#pragma unroll
        for (int i = 0; i < 4; i++)
#pragma unroll
            for (int jj = 0; jj < 4; jj++) a[i][jj] = 0.f;
        for (int d = 0; d < 128; d += 4) {
            float4 qv[4], kv[4];
#pragma unroll
            for (int i = 0; i < 4; i++) qv[i] = *(const float4*)&qs[(s0 + i) * 128 + d];
#pragma unroll
            for (int jj = 0; jj < 4; jj++) kv[jj] = *(const float4*)&ks[(t0 + jj) * 132 + d];
#pragma unroll
            for (int i = 0; i < 4; i++)
#pragma unroll
                for (int jj = 0; jj < 4; jj++)
                    a[i][jj] += qv[i].x * kv[jj].x + qv[i].y * kv[jj].y
                              + qv[i].z * kv[jj].z + qv[i].w * kv[jj].w;
        }
#pragma unroll
        for (int i = 0; i < 4; i++)
#pragma unroll
            for (int jj = 0; jj < 4; jj++)
                ps[(s0 + i) * 132 + t0 + jj] = a[i][jj] * scale;
    }
    __syncthreads();

    int w = tid >> 5, l = tid & 31;
    for (int s = w; s < 64; s += 8) {
        float* pr = ps + s * 132;
        float mx = -1e30f;
        for (int t = l; t < 132; t += 32) mx = fmaxf(mx, pr[t]);
#pragma unroll
        for (int o = 16; o; o >>= 1) mx = fmaxf(mx, __shfl_xor_sync(0xffffffffu, mx, o));
        float sum = 0.f;
        for (int t = l; t < 132; t += 32) {
            float e = __expf(pr[t] - mx);
            pr[t] = e;
            sum += e;
        }
#pragma unroll
        for (int o = 16; o; o >>= 1) sum += __shfl_xor_sync(0xffffffffu, sum, o);
        float inv = 1.f / sum;
        for (int t = l; t < 132; t += 32) pr[t] *= inv;
    }
    __syncthreads();

    for (int tile = tid; tile < 16 * 32; tile += 256) {
        int st = tile >> 5, dt = tile & 31;
        int s0 = st * 4, d0 = dt * 4;
        float4 acc[4];
#pragma unroll
        for (int i = 0; i < 4; i++) acc[i] = make_float4(0.f, 0.f, 0.f, 0.f);
        for (int t = 0; t < 132; t += 4) {
            float4 pv[4], vv[4];
#pragma unroll
            for (int i = 0; i < 4; i++) pv[i] = *(const float4*)&ps[(s0 + i) * 132 + t];
#pragma unroll
            for (int jj = 0; jj < 4; jj++) vv[jj] = *(const float4*)&vs[(t + jj) * 132 + d0];
#pragma unroll
            for (int i = 0; i < 4; i++) {
                acc[i].x += pv[i].x * vv[0].x + pv[i].y * vv[1].x + pv[i].z * vv[2].x + pv[i].w * vv[3].x;
                acc[i].y += pv[i].x * vv[0].y + pv[i].y * vv[1].y + pv[i].z * vv[2].y + pv[i].w * vv[3].y;
                acc[i].z += pv[i].x * vv[0].z + pv[i].y * vv[1].z + pv[i].z * vv[2].z + pv[i].w * vv[3].z;
                acc[i].w += pv[i].x * vv[0].w + pv[i].y * vv[1].w + pv[i].z * vv[2].w + pv[i].w * vv[3].w;
            }
        }
#pragma unroll
        for (int i = 0; i < 4; i++) {
            size_t o = (size_t)(seg * SEGS + s0 + i) * CDIM + h * HD + d0;
            float y[4] = {acc[i].x, acc[i].y, acc[i].z, acc[i].w};
            union { __nv_bfloat162 b2[2]; uint2 u; } H, L;
#pragma unroll
            for (int jj = 0; jj < 2; jj++) {
                __nv_bfloat16 h0 = __float2bfloat16(y[2 * jj]);
                __nv_bfloat16 h1 = __float2bfloat16(y[2 * jj + 1]);
                H.b2[jj] = __nv_bfloat162(h0, h1);
                L.b2[jj] = __nv_bfloat162(
                    __float2bfloat16(y[2 * jj] - __bfloat162float(h0)),
                    __float2bfloat16(y[2 * jj + 1] - __bfloat162float(h1)));
            }
            *(uint2*)(oh + o) = H.u;
            *(uint2*)(ol + o) = L.u;
        }
    }
}

// ---- z = sigmoid(gate)*attno + x  -> bf16 h/l -----------------------------
__global__ void combine_k(const float* __restrict__ gl, const float* __restrict__ ao,
                          const float* __restrict__ x,
                          __nv_bfloat16* __restrict__ zh, __nv_bfloat16* __restrict__ zl,
                          int n4)
{
    int i = blockIdx.x * blockDim.x + threadIdx.x;
    if (i >= n4) return;
    float4 gv = ((const float4*)gl)[i];
    float4 av = ((const float4*)ao)[i];
    float4 xv = ((const float4*)x)[i];
    float y[4];
    y[0] = av.x / (1.f + __expf(-gv.x)) + xv.x;
    y[1] = av.y / (1.f + __expf(-gv.y)) + xv.y;
    y[2] = av.z / (1.f + __expf(-gv.z)) + xv.z;
    y[3] = av.w / (1.f + __expf(-gv.w)) + xv.w;
    union { __nv_bfloat162 b2[2]; uint2 u; } H, L;
#pragma unroll
    for (int jj = 0; jj < 2; jj++) {
        __nv_bfloat16 h0 = __float2bfloat16(y[2 * jj]);
        __nv_bfloat16 h1 = __float2bfloat16(y[2 * jj + 1]);
        H.b2[jj] = __nv_bfloat162(h0, h1);
        L.b2[jj] = __nv_bfloat162(
            __float2bfloat16(y[2 * jj] - __bfloat162float(h0)),
            __float2bfloat16(y[2 * jj + 1] - __bfloat162float(h1)));
    }
    ((uint2*)zh)[i] = H.u;
    ((uint2*)zl)[i] = L.u;
}

// ---------------------------------------------------------------------------
extern "C" void kernel_launch(void* const* d_in, const int* in_sizes, int n_in,
                              void* d_out, int out_size)
{
    (void)in_sizes; (void)n_in; (void)out_size;
    const float* x        = (const float*)d_in[0];
    const float* pm       = (const float*)d_in[1];
    const float* Wq       = (const float*)d_in[2];
    const float* Wk       = (const float*)d_in[3];
    const float* Wv       = (const float*)d_in[4];
    const float* mem_W1   = (const float*)d_in[5];
    const float* mem_b1   = (const float*)d_in[6];
    const float* ln1_g    = (const float*)d_in[7];
    const float* ln1_b    = (const float*)d_in[8];
    const float* mem_W2   = (const float*)d_in[9];
    const float* mem_b2   = (const float*)d_in[10];
    const float* ln2_g    = (const float*)d_in[11];
    const float* ln2_b    = (const float*)d_in[12];
    const float* mem_outW = (const float*)d_in[13];
    const float* mem_outb = (const float*)d_in[14];
    const float* mstate   = (const float*)d_in[15];
    const float* mha_Wq   = (const float*)d_in[16];
    const float* mha_bq   = (const float*)d_in[17];
    const float* mha_Wk   = (const float*)d_in[18];
    const float* mha_bk   = (const float*)d_in[19];
    const float* mha_Wv   = (const float*)d_in[20];
    const float* mha_bv   = (const float*)d_in[21];
    const float* mha_Wo   = (const float*)d_in[22];
    const float* mha_bo   = (const float*)d_in[23];
    const float* gn_g     = (const float*)d_in[24];
    const float* gn_b     = (const float*)d_in[25];
    const float* gate_W   = (const float*)d_in[26];
    const float* gate_b   = (const float*)d_in[27];
    const float* out_W    = (const float*)d_in[28];
    const float* out_b    = (const float*)d_in[29];
    float* out = (float*)d_out;

    float *K2, *V2, *kpm, *vpm, *bkret, *bvret;
    float *mA, *qb, *kctx, *vctx, *attno, *gate;
    __nv_bfloat16 *xh, *xl, *sh, *sl, *mbh, *mbl;
    __nv_bfloat16 *q2h, *q2l, *k2h, *k2l, *v2h, *v2l, *amh, *aml;
    __nv_bfloat16 *kmh, *kml, *vmh, *vml, *woh, *wol, *gwh, *gwl, *owh, *owl;
    __nv_bfloat16 *mwqh, *mwql, *mwkh, *mwkl, *mwvh, *mwvl;
    __nv_bfloat16 *wqth, *wqtl, *wkth, *wktl, *wvth, *wvtl;
    __nv_bfloat16 *mw1h, *mw1l, *mowth, *mowtl, *w2h, *w2l;
    cudaGetSymbolAddress((void**)&K2, g_K2);
    cudaGetSymbolAddress((void**)&V2, g_V2);
    cudaGetSymbolAddress((void**)&kpm, g_kpm);
    cudaGetSymbolAddress((void**)&vpm, g_vpm);
    cudaGetSymbolAddress((void**)&bkret, g_bkret);
    cudaGetSymbolAddress((void**)&bvret, g_bvret);
    cudaGetSymbolAddress((void**)&mA, g_mA);
    cudaGetSymbolAddress((void**)&qb, g_qb);
    cudaGetSymbolAddress((void**)&kctx, g_kctx);
    cudaGetSymbolAddress((void**)&vctx, g_vctx);
    cudaGetSymbolAddress((void**)&attno, g_attno);
    cudaGetSymbolAddress((void**)&gate, g_gate);
    cudaGetSymbolAddress((void**)&xh, g_xh);   cudaGetSymbolAddress((void**)&xl, g_xl);
    cudaGetSymbolAddress((void**)&sh, g_sh);   cudaGetSymbolAddress((void**)&sl, g_sl);
    cudaGetSymbolAddress((void**)&mbh, g_mbh); cudaGetSymbolAddress((void**)&mbl, g_mbl);
    cudaGetSymbolAddress((void**)&q2h, g_q2h); cudaGetSymbolAddress((void**)&q2l, g_q2l);
    cudaGetSymbolAddress((void**)&k2h, g_k2h); cudaGetSymbolAddress((void**)&k2l, g_k2l);
    cudaGetSymbolAddress((void**)&v2h, g_v2h); cudaGetSymbolAddress((void**)&v2l, g_v2l);
    cudaGetSymbolAddress((void**)&amh, g_amh); cudaGetSymbolAddress((void**)&aml, g_aml);
    cudaGetSymbolAddress((void**)&kmh, g_kmh); cudaGetSymbolAddress((void**)&kml, g_kml);
    cudaGetSymbolAddress((void**)&vmh, g_vmh); cudaGetSymbolAddress((void**)&vml, g_vml);
    cudaGetSymbolAddress((void**)&woh, g_woh); cudaGetSymbolAddress((void**)&wol, g_wol);
    cudaGetSymbolAddress((void**)&gwh, g_gwh); cudaGetSymbolAddress((void**)&gwl, g_gwl);
    cudaGetSymbolAddress((void**)&owh, g_owh); cudaGetSymbolAddress((void**)&owl, g_owl);
    cudaGetSymbolAddress((void**)&mwqh, g_mwqh); cudaGetSymbolAddress((void**)&mwql, g_mwql);
    cudaGetSymbolAddress((void**)&mwkh, g_mwkh); cudaGetSymbolAddress((void**)&mwkl, g_mwkl);
    cudaGetSymbolAddress((void**)&mwvh, g_mwvh); cudaGetSymbolAddress((void**)&mwvl, g_mwvl);
    cudaGetSymbolAddress((void**)&wqth, g_wqth); cudaGetSymbolAddress((void**)&wqtl, g_wqtl);
    cudaGetSymbolAddress((void**)&wkth, g_wkth); cudaGetSymbolAddress((void**)&wktl, g_wktl);
    cudaGetSymbolAddress((void**)&wvth, g_wvth); cudaGetSymbolAddress((void**)&wvtl, g_wvtl);
    cudaGetSymbolAddress((void**)&mw1h, g_mw1h); cudaGetSymbolAddress((void**)&mw1l, g_mw1l);
    cudaGetSymbolAddress((void**)&mowth, g_mowth); cudaGetSymbolAddress((void**)&mowtl, g_mowtl);
    cudaGetSymbolAddress((void**)&w2h, g_w2h); cudaGetSymbolAddress((void**)&w2l, g_w2l);

    static bool attr_done = false;
    if (!attr_done) {
        cudaFuncSetAttribute(attn_k, cudaFuncAttributeMaxDynamicSharedMemorySize, ATTN_SMEM);
        cudaFuncSetAttribute(tmma_k, cudaFuncAttributeMaxDynamicSharedMemorySize, TM_SMEM);
        attr_done = true;
    }

    const int BIG = 1 << 30;

    TgBatch tb;
    auto tb_reset = [&]() { tb.njobs = 0; tb.prefix[0] = 0; };
    auto tb_add = [&](const __nv_bfloat16* ah, const __nv_bfloat16* al,
                      const __nv_bfloat16* bh, const __nv_bfloat16* bl,
                      const float* bias, float* C, __nv_bfloat16* Ch, __nv_bfloat16* Cl,
                      int M, int N, int K, int sr, int ss, int ro) {
        int j = tb.njobs++;
        tb.tilesN[j] = N / 128;
        tb.prefix[j + 1] = tb.prefix[j] + (M / 128) * (N / 128);
        tb.Ah[j] = ah; tb.Al[j] = al; tb.Bh[j] = bh; tb.Bl[j] = bl;
        tb.bias[j] = bias; tb.C[j] = C; tb.Ch[j] = Ch; tb.Cl[j] = Cl;
        tb.K[j] = K; tb.N[j] = N; tb.sr[j] = sr; tb.ss[j] = ss; tb.ro[j] = ro;
    };
    auto tb_go = [&]() {
        tmma_k<<<tb.prefix[tb.njobs], 256, TM_SMEM>>>(tb);
    };

    // ---- L0: all plain splits in ONE launch ----
    SpBatch sp; sp.njobs = 0; sp.prefix[0] = 0;
    auto sp_add = [&](const float* in, __nv_bfloat16* h, __nv_bfloat16* l, int n) {
        int j = sp.njobs++;
        sp.prefix[j + 1] = sp.prefix[j] + n / 8;
        sp.in[j] = in; sp.h[j] = h; sp.l[j] = l;
    };
    sp_add(x, xh, xl, NROWS * CDIM);
    sp_add(mha_Wq, mwqh, mwql, CDIM * CDIM);
    sp_add(mha_Wk, mwkh, mwkl, CDIM * CDIM);
    sp_add(mha_Wv, mwvh, mwvl, CDIM * CDIM);
    sp_add(mem_W1, mw1h, mw1l, MDIM * CDIM);
    sp_add(mem_W2, w2h, w2l, MDIM * MDIM);
    sp_add(mha_Wo, woh, wol, CDIM * CDIM);
    sp_add(gate_W, gwh, gwl, CDIM * CDIM);
    sp_add(out_W, owh, owl, CDIM * CDIM);
    split_k<<<(sp.prefix[sp.njobs] + 255) / 256, 256>>>(sp);

    // ---- L1: all transpose+splits in ONE launch ----
    TsBatch ts;
    ts.in[0] = Wq; ts.h[0] = wqth; ts.l[0] = wqtl; ts.R[0] = 1024; ts.Cc[0] = 1024;
    ts.in[1] = Wk; ts.h[1] = wkth; ts.l[1] = wktl; ts.R[1] = 1024; ts.Cc[1] = 1024;
    ts.in[2] = Wv; ts.h[2] = wvth; ts.l[2] = wvtl; ts.R[2] = 1024; ts.Cc[2] = 1024;
    ts.in[3] = mem_outW; ts.h[3] = mowth; ts.l[3] = mowtl; ts.R[3] = 1024; ts.Cc[3] = 128;
    tsplit_k<<<dim3(32, 32, 4), dim3(32, 8)>>>(ts);

    // ---- L2: batch {Q2, K2, V2, Amat} ----
    tb_reset();
    tb_add(mwqh, mwql, wqth, wqtl, nullptr, nullptr, q2h, q2l, 1024, 1024, 1024, BIG, 0, 0);
    tb_add(mwkh, mwkl, wkth, wktl, nullptr, K2, k2h, k2l, 1024, 1024, 1024, BIG, 0, 0);
    tb_add(mwvh, mwvl, wvth, wvtl, nullptr, V2, v2h, v2l, 1024, 1024, 1024, BIG, 0, 0);
    tb_add(mw1h, mw1l, wqth, wqtl, nullptr, nullptr, amh, aml, 128, 1024, 1024, BIG, 0, 0);
    tb_go();

    // ---- L3+L5 merged: {q,k,v-proj, KM, VM, memnet1} ----
    tb_reset();
    tb_add(xh, xl, q2h, q2l, mha_bq, qb, nullptr, nullptr, NROWS, 1024, 1024, BIG, 0, 0);
    tb_add(xh, xl, k2h, k2l, mha_bk, kctx, nullptr, nullptr, NROWS, 1024, 1024, SEGS, TCTX, SEGS + PDIM);
    tb_add(xh, xl, v2h, v2l, mha_bv, vctx, nullptr, nullptr, NROWS, 1024, 1024, SEGS, TCTX, SEGS + PDIM);
    tb_add(k2h, k2l, mowth, mowtl, nullptr, nullptr, kmh, kml, 1024, 128, 1024, BIG, 0, 0);
    tb_add(v2h, v2l, mowth, mowtl, nullptr, nullptr, vmh, vml, 1024, 128, 1024, BIG, 0, 0);
    tb_add(xh, xl, amh, aml, mem_b1, mA, nullptr, nullptr, NROWS, 128, 1024, BIG, 0, 0);
    tb_go();

    // ---- memnorm1 ----
    memnorm_k<<<NROWS, 128>>>(mA, ln1_g, ln1_b, nullptr, sh, sl, 1);

    // ---- memory net part 2 ----
    tb_reset();
    tb_add(sh, sl, w2h, w2l, mem_b2, mA, nullptr, nullptr, NROWS, 128, 128, BIG, 0, 0);
    tb_go();
    memnorm_k<<<NROWS, 128>>>(mA, ln2_g, ln2_b, mstate, mbh, mbl, 0);

    pmproj_k<<<32, 256>>>(pm, K2, V2, mha_bk, mha_bv, kpm, vpm);
    bias_ret_k<<<8, 256>>>(K2, V2, mem_outb, mha_bk, mha_bv, bkret, bvret);

    // ---- batch {k-ret, v-ret} ----
    tb_reset();
    tb_add(mbh, mbl, kmh, kml, bkret, kctx, nullptr, nullptr, NROWS, 1024, 128, SEGS, TCTX, 0);
    tb_add(mbh, mbl, vmh, vml, bvret, vctx, nullptr, nullptr, NROWS, 1024, 128, SEGS, TCTX, 0);
    tb_go();

    copy_pm_k<<<(NSEG * PDIM * CDIM + 255) / 256, 256>>>(kpm, vpm, kctx, vctx);

    // ---- attention -> bf16 h/l directly ----
    attn_k<<<dim3(HEADS, NSEG), 256, ATTN_SMEM>>>(qb, kctx, vctx, sh, sl);

    // ---- output projection, gate, final ----
    tb_reset();
    tb_add(sh, sl, woh, wol, mha_bo, attno, nullptr, nullptr, NROWS, 1024, 1024, BIG, 0, 0);
    tb_go();
    ln1024_k<<<NROWS, 256>>>(attno, gn_g, gn_b, sh, sl);
    tb_reset();
    tb_add(sh, sl, gwh, gwl, gate_b, gate, nullptr, nullptr, NROWS, 1024, 1024, BIG, 0, 0);
    tb_go();
    combine_k<<<(NROWS * CDIM / 4 + 255) / 256, 256>>>(gate, attno, x, sh, sl, NROWS * CDIM / 4);
    tb_reset();
    tb_add(sh, sl, owh, owl, out_b, out, nullptr, nullptr, NROWS, 1024, 1024, BIG, 0, 0);
    tb_go();
}